// round 9
// baseline (speedup 1.0000x reference)
#include <cuda_runtime.h>
#include <cuda_fp16.h>
#include <cstdint>
#include <cstddef>

// ======================= problem dims (fixed) =======================
#define T_STEPS 25
#define BATCH   1024
#define IN_DIM  1024
#define HID_DIM 4096
#define OUT_DIM 64
#define M_ROWS  (T_STEPS * BATCH)   // 25600

#define LO_SCALE     1024.0f
#define LO_INV_SCALE 0.0009765625f  // exact 2^-10

// ======================= static device scratch =======================
__device__ __half g_A    [(size_t)M_ROWS * IN_DIM];     // fp16 input spikes (exact 0/1)
__device__ __half g_w1hi [(size_t)HID_DIM * IN_DIM];
__device__ __half g_w1lo [(size_t)HID_DIM * IN_DIM];    // (w - hi) * 1024, fp16-normal
__device__ __half g_w2hi [(size_t)OUT_DIM * HID_DIM];
__device__ __half g_w2lo [(size_t)OUT_DIM * HID_DIM];
__device__ float  g_cur1 [(size_t)M_ROWS * HID_DIM];    // layer-1 currents
__device__ __half g_spk1 [(size_t)M_ROWS * HID_DIM];    // layer-1 spikes (exact 0/1)
__device__ float  g_cur2 [(size_t)M_ROWS * OUT_DIM];    // layer-2 currents

// ======================= helpers =======================
__device__ __forceinline__ void cp16(void* dst_smem, const void* src_gmem) {
    uint32_t d = (uint32_t)__cvta_generic_to_shared(dst_smem);
    asm volatile("cp.async.cg.shared.global [%0], [%1], 16;" :: "r"(d), "l"(src_gmem));
}
__device__ __forceinline__ void cp_commit() { asm volatile("cp.async.commit_group;"); }
__device__ __forceinline__ void cp_wait1()  { asm volatile("cp.async.wait_group 1;"); }
__device__ __forceinline__ void cp_wait0()  { asm volatile("cp.async.wait_group 0;"); }

__device__ __forceinline__ void ldsm_x4(uint32_t* r, uint32_t saddr) {
    asm volatile("ldmatrix.sync.aligned.m8n8.x4.shared.b16 {%0,%1,%2,%3}, [%4];"
        : "=r"(r[0]), "=r"(r[1]), "=r"(r[2]), "=r"(r[3]) : "r"(saddr));
}

__device__ __forceinline__ void mma16816(float* c, const uint32_t* a, uint32_t b0, uint32_t b1) {
    asm volatile(
        "mma.sync.aligned.m16n8k16.row.col.f32.f16.f16.f32 "
        "{%0,%1,%2,%3}, {%4,%5,%6,%7}, {%8,%9}, {%0,%1,%2,%3};"
        : "+f"(c[0]), "+f"(c[1]), "+f"(c[2]), "+f"(c[3])
        : "r"(a[0]), "r"(a[1]), "r"(a[2]), "r"(a[3]), "r"(b0), "r"(b1));
}

// ======================= prep kernels (vectorized) =======================
__global__ void k_cvt_spikes(const float4* __restrict__ x, __half2* __restrict__ y, int n4) {
    for (int i = blockIdx.x * blockDim.x + threadIdx.x; i < n4; i += gridDim.x * blockDim.x) {
        float4 v = x[i];
        y[2 * i]     = __floats2half2_rn(v.x, v.y);   // 0/1 -> exact fp16
        y[2 * i + 1] = __floats2half2_rn(v.z, v.w);
    }
}

__global__ void k_split(const float4* __restrict__ w, __half2* __restrict__ hi,
                        __half2* __restrict__ lo, int n4) {
    for (int i = blockIdx.x * blockDim.x + threadIdx.x; i < n4; i += gridDim.x * blockDim.x) {
        float4 v = w[i];
        __half h0 = __float2half_rn(v.x), h1 = __float2half_rn(v.y);
        __half h2 = __float2half_rn(v.z), h3 = __float2half_rn(v.w);
        hi[2 * i]     = __halves2half2(h0, h1);
        hi[2 * i + 1] = __halves2half2(h2, h3);
        lo[2 * i] = __floats2half2_rn(
            __fmul_rn(__fsub_rn(v.x, __half2float(h0)), LO_SCALE),
            __fmul_rn(__fsub_rn(v.y, __half2float(h1)), LO_SCALE));
        lo[2 * i + 1] = __floats2half2_rn(
            __fmul_rn(__fsub_rn(v.z, __half2float(h2)), LO_SCALE),
            __fmul_rn(__fsub_rn(v.w, __half2float(h3)), LO_SCALE));
    }
}

// ====== GEMM: C[M,N] = A[M,K] @ (Whi + Wlo/1024)[N,K]^T + bias (two-plane accum) ======
// 2-stage cp.async; ldmatrix.x4 fragment loads; separate fp32 accumulators per plane,
// combined as acc_hi + acc_lo/1024 + bias in the epilogue. Streaming C stores.
template <int BM, int BN, int BK, int WM, int WN, int MINCTA>
__global__ void __launch_bounds__((BM / WM) * (BN / WN) * 32, MINCTA)
gemm_hilo(const __half* __restrict__ A,
          const __half* __restrict__ Whi,
          const __half* __restrict__ Wlo,
          const float* __restrict__ bias,
          float* __restrict__ C,
          int M, int N, int K)
{
    constexpr int BKP  = BK + 8;                 // padded k-stride (halves); 144B rows
    constexpr int NW   = (BM / WM) * (BN / WN);
    constexpr int NTH  = NW * 32;
    constexpr int MT   = WM / 16;
    constexpr int NT   = WN / 8;                 // must be even (paired ldmatrix)
    constexpr int KCH  = BK / 8;                 // 16B chunks per row
    constexpr int ACH  = BM * KCH;
    constexpr int BCH  = BN * KCH;

    extern __shared__ __align__(16) unsigned char smem_raw[];
    __half* As = reinterpret_cast<__half*>(smem_raw);   // [2][BM][BKP]
    __half* Bs = As + 2 * BM * BKP;                      // [2][2][BN][BKP]  (stage, plane)

    const int tid  = threadIdx.x;
    const int wid  = tid >> 5;
    const int lane = tid & 31;

    const int wm0 = (wid % (BM / WM)) * WM;
    const int wn0 = (wid / (BM / WM)) * WN;
    const int bm0 = blockIdx.y * BM;
    const int bn0 = blockIdx.x * BN;
    const int NK  = K / BK;

    // ldmatrix.x4: lane L supplies the row address (L&7) of matrix (L>>3).
    const int mi = lane >> 3, rr = lane & 7;
    const int a_roff = (mi & 1) * 8 + rr;   // A: (m,k),(m+8,k),(m,k+8),(m+8,k+8)
    const int a_coff = (mi >> 1) * 8;
    const int b_roff = (mi >> 1) * 8 + rr;  // B: (n,k),(n,k+8),(n+8,k),(n+8,k+8)
    const int b_coff = (mi & 1) * 8;

    const uint32_t as_u = (uint32_t)__cvta_generic_to_shared(As);
    const uint32_t bs_u = (uint32_t)__cvta_generic_to_shared(Bs);

    float acc_h[MT][NT][4];
    float acc_l[MT][NT][4];
#pragma unroll
    for (int i = 0; i < MT; i++)
#pragma unroll
        for (int j = 0; j < NT; j++)
#pragma unroll
            for (int e = 0; e < 4; e++) { acc_h[i][j][e] = 0.f; acc_l[i][j][e] = 0.f; }

    auto load_stage = [&](int stage, int kt) {
        const int k0 = kt * BK;
#pragma unroll
        for (int c = tid; c < ACH; c += NTH) {
            int row = c / KCH, kc = (c % KCH) * 8;
            cp16(&As[(stage * BM + row) * BKP + kc],
                 A + (size_t)(bm0 + row) * K + k0 + kc);
        }
#pragma unroll
        for (int c = tid; c < BCH; c += NTH) {
            int row = c / KCH, kc = (c % KCH) * 8;
            size_t g = (size_t)(bn0 + row) * K + k0 + kc;
            cp16(&Bs[((stage * 2 + 0) * BN + row) * BKP + kc], Whi + g);
            cp16(&Bs[((stage * 2 + 1) * BN + row) * BKP + kc], Wlo + g);
        }
    };

    load_stage(0, 0);
    cp_commit();

    for (int kt = 0; kt < NK; kt++) {
        const int buf = kt & 1;
        if (kt + 1 < NK) {
            load_stage(buf ^ 1, kt + 1);
            cp_commit();
            cp_wait1();
        } else {
            cp_wait0();
        }
        __syncthreads();

#pragma unroll
        for (int kk = 0; kk < BK / 16; kk++) {
            uint32_t a[MT][4];
#pragma unroll
            for (int i = 0; i < MT; i++)
                ldsm_x4(a[i], as_u +
                    (uint32_t)(((buf * BM + wm0 + i * 16 + a_roff) * BKP
                                + kk * 16 + a_coff) * 2));
#pragma unroll
            for (int jp = 0; jp < NT / 2; jp++) {
                uint32_t b[4];
                ldsm_x4(b, bs_u +
                    (uint32_t)((((buf * 2 + 0) * BN + wn0 + jp * 16 + b_roff) * BKP
                                + kk * 16 + b_coff) * 2));
#pragma unroll
                for (int i = 0; i < MT; i++) mma16816(acc_h[i][2 * jp],     a[i], b[0], b[1]);
#pragma unroll
                for (int i = 0; i < MT; i++) mma16816(acc_h[i][2 * jp + 1], a[i], b[2], b[3]);
            }
#pragma unroll
            for (int jp = 0; jp < NT / 2; jp++) {
                uint32_t b[4];
                ldsm_x4(b, bs_u +
                    (uint32_t)((((buf * 2 + 1) * BN + wn0 + jp * 16 + b_roff) * BKP
                                + kk * 16 + b_coff) * 2));
#pragma unroll
                for (int i = 0; i < MT; i++) mma16816(acc_l[i][2 * jp],     a[i], b[0], b[1]);
#pragma unroll
                for (int i = 0; i < MT; i++) mma16816(acc_l[i][2 * jp + 1], a[i], b[2], b[3]);
            }
        }
        __syncthreads();
    }

    // epilogue: C = acc_hi + acc_lo/1024 + bias  (streaming stores)
    const int grp = lane >> 2, q = lane & 3;
#pragma unroll
    for (int i = 0; i < MT; i++) {
#pragma unroll
        for (int j = 0; j < NT; j++) {
            int row0 = bm0 + wm0 + i * 16 + grp;
            int row1 = row0 + 8;
            int col  = bn0 + wn0 + j * 8 + q * 2;
            float bv0 = bias[col];
            float bv1 = bias[col + 1];
            float v00 = fmaf(acc_l[i][j][0], LO_INV_SCALE, acc_h[i][j][0]) + bv0;
            float v01 = fmaf(acc_l[i][j][1], LO_INV_SCALE, acc_h[i][j][1]) + bv1;
            float v10 = fmaf(acc_l[i][j][2], LO_INV_SCALE, acc_h[i][j][2]) + bv0;
            float v11 = fmaf(acc_l[i][j][3], LO_INV_SCALE, acc_h[i][j][3]) + bv1;
            __stcs((float2*)&C[(size_t)row0 * N + col], make_float2(v00, v01));
            __stcs((float2*)&C[(size_t)row1 * N + col], make_float2(v10, v11));
        }
    }
}

// ======================= LIF layer 1: currents -> spikes (fp16) =======================
// mem_t = 0.9*mem + cur_t - spk_{t-1};  spk_t = (mem_t - 1 > 0). _rn ops forbid FMA fusion.
__global__ void lif1_kernel(const float* __restrict__ cur, __half* __restrict__ spk) {
    int idx = blockIdx.x * blockDim.x + threadIdx.x;   // = b*HID + h
    if (idx >= BATCH * HID_DIM) return;
    float mem = 0.f, sp = 0.f;
#pragma unroll
    for (int t = 0; t < T_STEPS; t++) {
        float c = __ldcs(&cur[(size_t)t * BATCH * HID_DIM + idx]);  // read-once stream
        mem = __fsub_rn(__fadd_rn(__fmul_rn(0.9f, mem), c), sp);
        sp  = (mem > 1.0f) ? 1.f : 0.f;
        spk[(size_t)t * BATCH * HID_DIM + idx] = __float2half_rn(sp);
    }
}

// ======================= LIF layer 2: currents -> spike counts =======================
__global__ void lif2_kernel(const float* __restrict__ cur, float* __restrict__ out) {
    int idx = blockIdx.x * blockDim.x + threadIdx.x;   // = b*OUT + o
    if (idx >= BATCH * OUT_DIM) return;
    float mem = 0.f, sp = 0.f, cnt = 0.f;
#pragma unroll
    for (int t = 0; t < T_STEPS; t++) {
        float c = __ldcs(&cur[(size_t)t * BATCH * OUT_DIM + idx]);
        mem = __fsub_rn(__fadd_rn(__fmul_rn(0.9f, mem), c), sp);
        sp  = (mem > 1.0f) ? 1.f : 0.f;
        cnt += sp;
    }
    out[idx] = cnt;
}

// ======================= launch =======================
extern "C" void kernel_launch(void* const* d_in, const int* in_sizes, int n_in,
                              void* d_out, int out_size) {
    const float* x  = (const float*)d_in[0];   // [25,1024,1024]
    const float* w1 = (const float*)d_in[1];   // [4096,1024]
    const float* b1 = (const float*)d_in[2];   // [4096]
    const float* w2 = (const float*)d_in[3];   // [64,4096]
    const float* b2 = (const float*)d_in[4];   // [64]
    float* out = (float*)d_out;                // [1024,64]

    __half *A, *w1hi, *w1lo, *w2hi, *w2lo, *spk1;
    float *cur1, *cur2;
    cudaGetSymbolAddress((void**)&A,    g_A);
    cudaGetSymbolAddress((void**)&w1hi, g_w1hi);
    cudaGetSymbolAddress((void**)&w1lo, g_w1lo);
    cudaGetSymbolAddress((void**)&w2hi, g_w2hi);
    cudaGetSymbolAddress((void**)&w2lo, g_w2lo);
    cudaGetSymbolAddress((void**)&spk1, g_spk1);
    cudaGetSymbolAddress((void**)&cur1, g_cur1);
    cudaGetSymbolAddress((void**)&cur2, g_cur2);

    // GEMM1 "slim": BM=64,BN=64,WM=16,WN=32 -> 8 warps, acc/warp=32 regs,
    //               minctasm=3 -> 24 warps/SM. smem/CTA = 2*(64*72 + 2*64*72)*2B = 55296.
    constexpr int SMEM1 = 2 * (64 * 72 + 2 * 64 * 72) * 2;
    // GEMM2 (round-5 proven): BM=128,BN=64,WM=32,WN=32 -> 8 warps, 2 CTAs/SM.
    constexpr int SMEM2 = 2 * (128 * 72 + 2 * 64 * 72) * 2;
    cudaFuncSetAttribute((const void*)gemm_hilo<64, 64, 64, 16, 32, 3>,
                         cudaFuncAttributeMaxDynamicSharedMemorySize, SMEM1);
    cudaFuncSetAttribute((const void*)gemm_hilo<128, 64, 64, 32, 32, 2>,
                         cudaFuncAttributeMaxDynamicSharedMemorySize, SMEM2);

    // 1) prep (vectorized)
    k_cvt_spikes<<<4096, 256>>>((const float4*)x, (__half2*)A, (M_ROWS * IN_DIM) / 4);
    k_split<<<2048, 256>>>((const float4*)w1, (__half2*)w1hi, (__half2*)w1lo,
                           (HID_DIM * IN_DIM) / 4);
    k_split<<<256, 256>>>((const float4*)w2, (__half2*)w2hi, (__half2*)w2lo,
                          (OUT_DIM * HID_DIM) / 4);

    // 2) GEMM1: cur1[25600,4096] = A[25600,1024] @ w1^T + b1  (grid 64x400, 24 warps/SM)
    gemm_hilo<64, 64, 64, 16, 32, 3>
        <<<dim3(HID_DIM / 64, M_ROWS / 64), 256, SMEM1>>>(
            A, w1hi, w1lo, b1, cur1, M_ROWS, HID_DIM, IN_DIM);

    // 3) LIF layer 1
    lif1_kernel<<<(BATCH * HID_DIM) / 256, 256>>>(cur1, spk1);

    // 4) GEMM2: cur2[25600,64] = spk1 @ w2^T + b2  (grid 1x200, round-5 config)
    gemm_hilo<128, 64, 64, 32, 32, 2>
        <<<dim3(OUT_DIM / 64, M_ROWS / 128), 256, SMEM2>>>(
            spk1, w2hi, w2lo, b2, cur2, M_ROWS, OUT_DIM, HID_DIM);

    // 5) LIF layer 2 + spike counting
    lif2_kernel<<<(BATCH * OUT_DIM) / 256, 256>>>(cur2, out);
}

// round 10
// speedup vs baseline: 1.2080x; 1.2080x over previous
#include <cuda_runtime.h>
#include <cuda_fp16.h>
#include <cstdint>
#include <cstddef>

// ======================= problem dims (fixed) =======================
#define T_STEPS 25
#define BATCH   1024
#define IN_DIM  1024
#define HID_DIM 4096
#define OUT_DIM 64
#define M_ROWS  (T_STEPS * BATCH)   // 25600

#define LO_SCALE     1024.0f
#define LO_INV_SCALE 0.0009765625f  // exact 2^-10

// ======================= static device scratch =======================
__device__ __half g_A    [(size_t)M_ROWS * IN_DIM];     // fp16 input spikes (exact 0/1)
__device__ __half g_w1hi [(size_t)HID_DIM * IN_DIM];
__device__ __half g_w1lo [(size_t)HID_DIM * IN_DIM];    // (w - hi) * 1024, fp16-normal
__device__ __half g_w2hi [(size_t)OUT_DIM * HID_DIM];
__device__ __half g_w2lo [(size_t)OUT_DIM * HID_DIM];
__device__ float  g_cur1 [(size_t)M_ROWS * HID_DIM];    // layer-1 currents
__device__ __half g_spk1 [(size_t)M_ROWS * HID_DIM];    // layer-1 spikes (exact 0/1)
__device__ float  g_cur2 [(size_t)M_ROWS * OUT_DIM];    // layer-2 currents

// ======================= helpers =======================
__device__ __forceinline__ void cp16(void* dst_smem, const void* src_gmem) {
    uint32_t d = (uint32_t)__cvta_generic_to_shared(dst_smem);
    asm volatile("cp.async.cg.shared.global [%0], [%1], 16;" :: "r"(d), "l"(src_gmem));
}
__device__ __forceinline__ void cp_commit() { asm volatile("cp.async.commit_group;"); }
__device__ __forceinline__ void cp_wait1()  { asm volatile("cp.async.wait_group 1;"); }
__device__ __forceinline__ void cp_wait0()  { asm volatile("cp.async.wait_group 0;"); }

__device__ __forceinline__ void ldsm_x4(uint32_t* r, uint32_t saddr) {
    asm volatile("ldmatrix.sync.aligned.m8n8.x4.shared.b16 {%0,%1,%2,%3}, [%4];"
        : "=r"(r[0]), "=r"(r[1]), "=r"(r[2]), "=r"(r[3]) : "r"(saddr));
}

__device__ __forceinline__ void mma16816(float* c, const uint32_t* a, uint32_t b0, uint32_t b1) {
    asm volatile(
        "mma.sync.aligned.m16n8k16.row.col.f32.f16.f16.f32 "
        "{%0,%1,%2,%3}, {%4,%5,%6,%7}, {%8,%9}, {%0,%1,%2,%3};"
        : "+f"(c[0]), "+f"(c[1]), "+f"(c[2]), "+f"(c[3])
        : "r"(a[0]), "r"(a[1]), "r"(a[2]), "r"(a[3]), "r"(b0), "r"(b1));
}

// ======================= prep kernels (vectorized) =======================
__global__ void k_cvt_spikes(const float4* __restrict__ x, __half2* __restrict__ y, int n4) {
    for (int i = blockIdx.x * blockDim.x + threadIdx.x; i < n4; i += gridDim.x * blockDim.x) {
        float4 v = x[i];
        y[2 * i]     = __floats2half2_rn(v.x, v.y);   // 0/1 -> exact fp16
        y[2 * i + 1] = __floats2half2_rn(v.z, v.w);
    }
}

__global__ void k_split(const float4* __restrict__ w, __half2* __restrict__ hi,
                        __half2* __restrict__ lo, int n4) {
    for (int i = blockIdx.x * blockDim.x + threadIdx.x; i < n4; i += gridDim.x * blockDim.x) {
        float4 v = w[i];
        __half h0 = __float2half_rn(v.x), h1 = __float2half_rn(v.y);
        __half h2 = __float2half_rn(v.z), h3 = __float2half_rn(v.w);
        hi[2 * i]     = __halves2half2(h0, h1);
        hi[2 * i + 1] = __halves2half2(h2, h3);
        lo[2 * i] = __floats2half2_rn(
            __fmul_rn(__fsub_rn(v.x, __half2float(h0)), LO_SCALE),
            __fmul_rn(__fsub_rn(v.y, __half2float(h1)), LO_SCALE));
        lo[2 * i + 1] = __floats2half2_rn(
            __fmul_rn(__fsub_rn(v.z, __half2float(h2)), LO_SCALE),
            __fmul_rn(__fsub_rn(v.w, __half2float(h3)), LO_SCALE));
    }
}

// ====== GEMM: C[M,N] = A[M,K] @ (Whi + Wlo/1024)[N,K]^T + bias (two-plane accum) ======
// 2-stage cp.async; ldmatrix.x4 fragment loads; separate fp32 accumulators per plane,
// combined as acc_hi + acc_lo/1024 + bias in the epilogue. Per-output accumulation
// order is strictly K-ascending and independent of BM/BN/WM/WN tiling (bit-safe).
template <int BM, int BN, int BK, int WM, int WN, int MINCTA>
__global__ void __launch_bounds__((BM / WM) * (BN / WN) * 32, MINCTA)
gemm_hilo(const __half* __restrict__ A,
          const __half* __restrict__ Whi,
          const __half* __restrict__ Wlo,
          const float* __restrict__ bias,
          float* __restrict__ C,
          int M, int N, int K)
{
    constexpr int BKP  = BK + 8;                 // padded k-stride (halves); 144B rows
    constexpr int NW   = (BM / WM) * (BN / WN);
    constexpr int NTH  = NW * 32;
    constexpr int MT   = WM / 16;
    constexpr int NT   = WN / 8;                 // must be even (paired ldmatrix)
    constexpr int KCH  = BK / 8;                 // 16B chunks per row
    constexpr int ACH  = BM * KCH;
    constexpr int BCH  = BN * KCH;

    extern __shared__ __align__(16) unsigned char smem_raw[];
    __half* As = reinterpret_cast<__half*>(smem_raw);   // [2][BM][BKP]
    __half* Bs = As + 2 * BM * BKP;                      // [2][2][BN][BKP]  (stage, plane)

    const int tid  = threadIdx.x;
    const int wid  = tid >> 5;
    const int lane = tid & 31;

    const int wm0 = (wid % (BM / WM)) * WM;
    const int wn0 = (wid / (BM / WM)) * WN;
    const int bm0 = blockIdx.y * BM;
    const int bn0 = blockIdx.x * BN;
    const int NK  = K / BK;

    // ldmatrix.x4: lane L supplies the row address (L&7) of matrix (L>>3).
    const int mi = lane >> 3, rr = lane & 7;
    const int a_roff = (mi & 1) * 8 + rr;   // A: (m,k),(m+8,k),(m,k+8),(m+8,k+8)
    const int a_coff = (mi >> 1) * 8;
    const int b_roff = (mi >> 1) * 8 + rr;  // B: (n,k),(n,k+8),(n+8,k),(n+8,k+8)
    const int b_coff = (mi & 1) * 8;

    const uint32_t as_u = (uint32_t)__cvta_generic_to_shared(As);
    const uint32_t bs_u = (uint32_t)__cvta_generic_to_shared(Bs);

    float acc_h[MT][NT][4];
    float acc_l[MT][NT][4];
#pragma unroll
    for (int i = 0; i < MT; i++)
#pragma unroll
        for (int j = 0; j < NT; j++)
#pragma unroll
            for (int e = 0; e < 4; e++) { acc_h[i][j][e] = 0.f; acc_l[i][j][e] = 0.f; }

    auto load_stage = [&](int stage, int kt) {
        const int k0 = kt * BK;
#pragma unroll
        for (int c = tid; c < ACH; c += NTH) {
            int row = c / KCH, kc = (c % KCH) * 8;
            cp16(&As[(stage * BM + row) * BKP + kc],
                 A + (size_t)(bm0 + row) * K + k0 + kc);
        }
#pragma unroll
        for (int c = tid; c < BCH; c += NTH) {
            int row = c / KCH, kc = (c % KCH) * 8;
            size_t g = (size_t)(bn0 + row) * K + k0 + kc;
            cp16(&Bs[((stage * 2 + 0) * BN + row) * BKP + kc], Whi + g);
            cp16(&Bs[((stage * 2 + 1) * BN + row) * BKP + kc], Wlo + g);
        }
    };

    load_stage(0, 0);
    cp_commit();

    for (int kt = 0; kt < NK; kt++) {
        const int buf = kt & 1;
        if (kt + 1 < NK) {
            load_stage(buf ^ 1, kt + 1);
            cp_commit();
            cp_wait1();
        } else {
            cp_wait0();
        }
        __syncthreads();

#pragma unroll
        for (int kk = 0; kk < BK / 16; kk++) {
            uint32_t a[MT][4];
#pragma unroll
            for (int i = 0; i < MT; i++)
                ldsm_x4(a[i], as_u +
                    (uint32_t)(((buf * BM + wm0 + i * 16 + a_roff) * BKP
                                + kk * 16 + a_coff) * 2));
#pragma unroll
            for (int jp = 0; jp < NT / 2; jp++) {
                uint32_t b[4];
                ldsm_x4(b, bs_u +
                    (uint32_t)((((buf * 2 + 0) * BN + wn0 + jp * 16 + b_roff) * BKP
                                + kk * 16 + b_coff) * 2));
#pragma unroll
                for (int i = 0; i < MT; i++) mma16816(acc_h[i][2 * jp],     a[i], b[0], b[1]);
#pragma unroll
                for (int i = 0; i < MT; i++) mma16816(acc_h[i][2 * jp + 1], a[i], b[2], b[3]);
            }
#pragma unroll
            for (int jp = 0; jp < NT / 2; jp++) {
                uint32_t b[4];
                ldsm_x4(b, bs_u +
                    (uint32_t)((((buf * 2 + 1) * BN + wn0 + jp * 16 + b_roff) * BKP
                                + kk * 16 + b_coff) * 2));
#pragma unroll
                for (int i = 0; i < MT; i++) mma16816(acc_l[i][2 * jp],     a[i], b[0], b[1]);
#pragma unroll
                for (int i = 0; i < MT; i++) mma16816(acc_l[i][2 * jp + 1], a[i], b[2], b[3]);
            }
        }
        __syncthreads();
    }

    // epilogue: C = acc_hi + acc_lo/1024 + bias  (streaming stores)
    const int grp = lane >> 2, q = lane & 3;
#pragma unroll
    for (int i = 0; i < MT; i++) {
#pragma unroll
        for (int j = 0; j < NT; j++) {
            int row0 = bm0 + wm0 + i * 16 + grp;
            int row1 = row0 + 8;
            int col  = bn0 + wn0 + j * 8 + q * 2;
            float bv0 = bias[col];
            float bv1 = bias[col + 1];
            float v00 = fmaf(acc_l[i][j][0], LO_INV_SCALE, acc_h[i][j][0]) + bv0;
            float v01 = fmaf(acc_l[i][j][1], LO_INV_SCALE, acc_h[i][j][1]) + bv1;
            float v10 = fmaf(acc_l[i][j][2], LO_INV_SCALE, acc_h[i][j][2]) + bv0;
            float v11 = fmaf(acc_l[i][j][3], LO_INV_SCALE, acc_h[i][j][3]) + bv1;
            __stcs((float2*)&C[(size_t)row0 * N + col], make_float2(v00, v01));
            __stcs((float2*)&C[(size_t)row1 * N + col], make_float2(v10, v11));
        }
    }
}

// ======================= LIF layer 1: currents -> spikes (fp16) =======================
// mem_t = 0.9*mem + cur_t - spk_{t-1};  spk_t = (mem_t - 1 > 0). _rn ops forbid FMA fusion.
__global__ void lif1_kernel(const float* __restrict__ cur, __half* __restrict__ spk) {
    int idx = blockIdx.x * blockDim.x + threadIdx.x;   // = b*HID + h
    if (idx >= BATCH * HID_DIM) return;
    float mem = 0.f, sp = 0.f;
#pragma unroll
    for (int t = 0; t < T_STEPS; t++) {
        float c = __ldcs(&cur[(size_t)t * BATCH * HID_DIM + idx]);  // read-once stream
        mem = __fsub_rn(__fadd_rn(__fmul_rn(0.9f, mem), c), sp);
        sp  = (mem > 1.0f) ? 1.f : 0.f;
        spk[(size_t)t * BATCH * HID_DIM + idx] = __float2half_rn(sp);
    }
}

// ======================= LIF layer 2: currents -> spike counts =======================
__global__ void lif2_kernel(const float* __restrict__ cur, float* __restrict__ out) {
    int idx = blockIdx.x * blockDim.x + threadIdx.x;   // = b*OUT + o
    if (idx >= BATCH * OUT_DIM) return;
    float mem = 0.f, sp = 0.f, cnt = 0.f;
#pragma unroll
    for (int t = 0; t < T_STEPS; t++) {
        float c = __ldcs(&cur[(size_t)t * BATCH * OUT_DIM + idx]);
        mem = __fsub_rn(__fadd_rn(__fmul_rn(0.9f, mem), c), sp);
        sp  = (mem > 1.0f) ? 1.f : 0.f;
        cnt += sp;
    }
    out[idx] = cnt;
}

// ======================= launch =======================
extern "C" void kernel_launch(void* const* d_in, const int* in_sizes, int n_in,
                              void* d_out, int out_size) {
    const float* x  = (const float*)d_in[0];   // [25,1024,1024]
    const float* w1 = (const float*)d_in[1];   // [4096,1024]
    const float* b1 = (const float*)d_in[2];   // [4096]
    const float* w2 = (const float*)d_in[3];   // [64,4096]
    const float* b2 = (const float*)d_in[4];   // [64]
    float* out = (float*)d_out;                // [1024,64]

    __half *A, *w1hi, *w1lo, *w2hi, *w2lo, *spk1;
    float *cur1, *cur2;
    cudaGetSymbolAddress((void**)&A,    g_A);
    cudaGetSymbolAddress((void**)&w1hi, g_w1hi);
    cudaGetSymbolAddress((void**)&w1lo, g_w1lo);
    cudaGetSymbolAddress((void**)&w2hi, g_w2hi);
    cudaGetSymbolAddress((void**)&w2lo, g_w2lo);
    cudaGetSymbolAddress((void**)&spk1, g_spk1);
    cudaGetSymbolAddress((void**)&cur1, g_cur1);
    cudaGetSymbolAddress((void**)&cur2, g_cur2);

    // GEMM1 (round-5 optimum): BM=128,BN=64,WM=32,WN=32 -> 8 warps, 2 CTAs/SM.
    constexpr int SMEM1 = 2 * (128 * 72 + 2 * 64 * 72) * 2;   // 73728 B
    // GEMM2: BM=64,BN=64,WM=32,WN=16 -> 8 warps, acc=32 regs, grid 400 (better balance).
    constexpr int SMEM2 = 2 * (64 * 72 + 2 * 64 * 72) * 2;    // 55296 B
    cudaFuncSetAttribute((const void*)gemm_hilo<128, 64, 64, 32, 32, 2>,
                         cudaFuncAttributeMaxDynamicSharedMemorySize, SMEM1);
    cudaFuncSetAttribute((const void*)gemm_hilo<64, 64, 64, 32, 16, 2>,
                         cudaFuncAttributeMaxDynamicSharedMemorySize, SMEM2);

    // 1) prep (vectorized)
    k_cvt_spikes<<<4096, 256>>>((const float4*)x, (__half2*)A, (M_ROWS * IN_DIM) / 4);
    k_split<<<2048, 256>>>((const float4*)w1, (__half2*)w1hi, (__half2*)w1lo,
                           (HID_DIM * IN_DIM) / 4);
    k_split<<<256, 256>>>((const float4*)w2, (__half2*)w2hi, (__half2*)w2lo,
                          (OUT_DIM * HID_DIM) / 4);

    // 2) GEMM1: cur1[25600,4096] = A[25600,1024] @ w1^T + b1  (grid 64x200)
    gemm_hilo<128, 64, 64, 32, 32, 2>
        <<<dim3(HID_DIM / 64, M_ROWS / 128), 256, SMEM1>>>(
            A, w1hi, w1lo, b1, cur1, M_ROWS, HID_DIM, IN_DIM);

    // 3) LIF layer 1
    lif1_kernel<<<(BATCH * HID_DIM) / 256, 256>>>(cur1, spk1);

    // 4) GEMM2: cur2[25600,64] = spk1 @ w2^T + b2  (grid 1x400, all CTAs resident)
    gemm_hilo<64, 64, 64, 32, 16, 2>
        <<<dim3(OUT_DIM / 64, M_ROWS / 64), 256, SMEM2>>>(
            spk1, w2hi, w2lo, b2, cur2, M_ROWS, OUT_DIM, HID_DIM);

    // 5) LIF layer 2 + spike counting
    lif2_kernel<<<(BATCH * OUT_DIM) / 256, 256>>>(cur2, out);
}

// round 11
// speedup vs baseline: 1.2601x; 1.0431x over previous
#include <cuda_runtime.h>
#include <cuda_fp16.h>
#include <cstdint>
#include <cstddef>

// ======================= problem dims (fixed) =======================
#define T_STEPS 25
#define BATCH   1024
#define IN_DIM  1024
#define HID_DIM 4096
#define OUT_DIM 64
#define M_ROWS  (T_STEPS * BATCH)   // 25600

#define LO_SCALE     1024.0f
#define LO_INV_SCALE 0.0009765625f  // exact 2^-10

// ======================= static device scratch =======================
__device__ __half g_A    [(size_t)M_ROWS * IN_DIM];     // fp16 input spikes (exact 0/1)
__device__ __half g_w1hi [(size_t)HID_DIM * IN_DIM];
__device__ __half g_w1lo [(size_t)HID_DIM * IN_DIM];    // (w - hi) * 1024, fp16-normal
__device__ __half g_w2hi [(size_t)OUT_DIM * HID_DIM];
__device__ __half g_w2lo [(size_t)OUT_DIM * HID_DIM];
__device__ float  g_cur1 [(size_t)M_ROWS * HID_DIM];    // layer-1 currents
__device__ __half g_spk1 [(size_t)M_ROWS * HID_DIM];    // layer-1 spikes (exact 0/1)
__device__ float  g_cur2 [(size_t)M_ROWS * OUT_DIM];    // layer-2 currents

// ======================= helpers =======================
__device__ __forceinline__ void cp16(void* dst_smem, const void* src_gmem) {
    uint32_t d = (uint32_t)__cvta_generic_to_shared(dst_smem);
    asm volatile("cp.async.cg.shared.global [%0], [%1], 16;" :: "r"(d), "l"(src_gmem));
}
__device__ __forceinline__ void cp_commit() { asm volatile("cp.async.commit_group;"); }
__device__ __forceinline__ void cp_wait1()  { asm volatile("cp.async.wait_group 1;"); }
__device__ __forceinline__ void cp_wait0()  { asm volatile("cp.async.wait_group 0;"); }

__device__ __forceinline__ void ldsm_x4(uint32_t* r, uint32_t saddr) {
    asm volatile("ldmatrix.sync.aligned.m8n8.x4.shared.b16 {%0,%1,%2,%3}, [%4];"
        : "=r"(r[0]), "=r"(r[1]), "=r"(r[2]), "=r"(r[3]) : "r"(saddr));
}

__device__ __forceinline__ void mma16816(float* c, const uint32_t* a, uint32_t b0, uint32_t b1) {
    asm volatile(
        "mma.sync.aligned.m16n8k16.row.col.f32.f16.f16.f32 "
        "{%0,%1,%2,%3}, {%4,%5,%6,%7}, {%8,%9}, {%0,%1,%2,%3};"
        : "+f"(c[0]), "+f"(c[1]), "+f"(c[2]), "+f"(c[3])
        : "r"(a[0]), "r"(a[1]), "r"(a[2]), "r"(a[3]), "r"(b0), "r"(b1));
}

// ======================= prep kernels =======================
__global__ void k_cvt_spikes(const float* __restrict__ x, __half* __restrict__ y, int n) {
    for (int i = blockIdx.x * blockDim.x + threadIdx.x; i < n; i += gridDim.x * blockDim.x)
        y[i] = __float2half_rn(x[i]);   // 0.0 / 1.0 -> exact fp16
}

__global__ void k_split(const float* __restrict__ w, __half* __restrict__ hi,
                        __half* __restrict__ lo, int n) {
    for (int i = blockIdx.x * blockDim.x + threadIdx.x; i < n; i += gridDim.x * blockDim.x) {
        float v = w[i];
        __half h = __float2half_rn(v);
        hi[i] = h;
        // residual scaled into fp16-normal range; own accumulator keeps planes
        // scale-homogeneous (tensor-core accum truncates tiny addends vs big C).
        lo[i] = __float2half_rn(__fmul_rn(__fsub_rn(v, __half2float(h)), LO_SCALE));
    }
}

// ====== GEMM: C[M,N] = A[M,K] @ (Whi + Wlo/1024)[N,K]^T + bias (two-plane accum) ======
// 2-stage cp.async; ldmatrix.x4 fragment loads; separate fp32 accumulators per plane,
// combined as acc_hi + acc_lo/1024 + bias in the epilogue. Per-output accumulation
// order is strictly K-ascending and independent of BM/BN/WM/WN tiling (bit-safe).
template <int BM, int BN, int BK, int WM, int WN, int MINCTA>
__global__ void __launch_bounds__((BM / WM) * (BN / WN) * 32, MINCTA)
gemm_hilo(const __half* __restrict__ A,
          const __half* __restrict__ Whi,
          const __half* __restrict__ Wlo,
          const float* __restrict__ bias,
          float* __restrict__ C,
          int M, int N, int K)
{
    constexpr int BKP  = BK + 8;                 // padded k-stride (halves); 144B rows
    constexpr int NW   = (BM / WM) * (BN / WN);
    constexpr int NTH  = NW * 32;
    constexpr int MT   = WM / 16;
    constexpr int NT   = WN / 8;                 // must be even (paired ldmatrix)
    constexpr int KCH  = BK / 8;                 // 16B chunks per row
    constexpr int ACH  = BM * KCH;
    constexpr int BCH  = BN * KCH;

    extern __shared__ __align__(16) unsigned char smem_raw[];
    __half* As = reinterpret_cast<__half*>(smem_raw);   // [2][BM][BKP]
    __half* Bs = As + 2 * BM * BKP;                      // [2][2][BN][BKP]  (stage, plane)

    const int tid  = threadIdx.x;
    const int wid  = tid >> 5;
    const int lane = tid & 31;

    const int wm0 = (wid % (BM / WM)) * WM;
    const int wn0 = (wid / (BM / WM)) * WN;
    const int bm0 = blockIdx.y * BM;
    const int bn0 = blockIdx.x * BN;
    const int NK  = K / BK;

    // ldmatrix.x4: lane L supplies the row address (L&7) of matrix (L>>3).
    const int mi = lane >> 3, rr = lane & 7;
    const int a_roff = (mi & 1) * 8 + rr;   // A: (m,k),(m+8,k),(m,k+8),(m+8,k+8)
    const int a_coff = (mi >> 1) * 8;
    const int b_roff = (mi >> 1) * 8 + rr;  // B: (n,k),(n,k+8),(n+8,k),(n+8,k+8)
    const int b_coff = (mi & 1) * 8;

    const uint32_t as_u = (uint32_t)__cvta_generic_to_shared(As);
    const uint32_t bs_u = (uint32_t)__cvta_generic_to_shared(Bs);

    float acc_h[MT][NT][4];
    float acc_l[MT][NT][4];
#pragma unroll
    for (int i = 0; i < MT; i++)
#pragma unroll
        for (int j = 0; j < NT; j++)
#pragma unroll
            for (int e = 0; e < 4; e++) { acc_h[i][j][e] = 0.f; acc_l[i][j][e] = 0.f; }

    auto load_stage = [&](int stage, int kt) {
        const int k0 = kt * BK;
#pragma unroll
        for (int c = tid; c < ACH; c += NTH) {
            int row = c / KCH, kc = (c % KCH) * 8;
            cp16(&As[(stage * BM + row) * BKP + kc],
                 A + (size_t)(bm0 + row) * K + k0 + kc);
        }
#pragma unroll
        for (int c = tid; c < BCH; c += NTH) {
            int row = c / KCH, kc = (c % KCH) * 8;
            size_t g = (size_t)(bn0 + row) * K + k0 + kc;
            cp16(&Bs[((stage * 2 + 0) * BN + row) * BKP + kc], Whi + g);
            cp16(&Bs[((stage * 2 + 1) * BN + row) * BKP + kc], Wlo + g);
        }
    };

    load_stage(0, 0);
    cp_commit();

    for (int kt = 0; kt < NK; kt++) {
        const int buf = kt & 1;
        if (kt + 1 < NK) {
            load_stage(buf ^ 1, kt + 1);
            cp_commit();
            cp_wait1();
        } else {
            cp_wait0();
        }
        __syncthreads();

#pragma unroll
        for (int kk = 0; kk < BK / 16; kk++) {
            uint32_t a[MT][4];
#pragma unroll
            for (int i = 0; i < MT; i++)
                ldsm_x4(a[i], as_u +
                    (uint32_t)(((buf * BM + wm0 + i * 16 + a_roff) * BKP
                                + kk * 16 + a_coff) * 2));
#pragma unroll
            for (int jp = 0; jp < NT / 2; jp++) {
                uint32_t b[4];
                ldsm_x4(b, bs_u +
                    (uint32_t)((((buf * 2 + 0) * BN + wn0 + jp * 16 + b_roff) * BKP
                                + kk * 16 + b_coff) * 2));
#pragma unroll
                for (int i = 0; i < MT; i++) mma16816(acc_h[i][2 * jp],     a[i], b[0], b[1]);
#pragma unroll
                for (int i = 0; i < MT; i++) mma16816(acc_h[i][2 * jp + 1], a[i], b[2], b[3]);
            }
#pragma unroll
            for (int jp = 0; jp < NT / 2; jp++) {
                uint32_t b[4];
                ldsm_x4(b, bs_u +
                    (uint32_t)((((buf * 2 + 1) * BN + wn0 + jp * 16 + b_roff) * BKP
                                + kk * 16 + b_coff) * 2));
#pragma unroll
                for (int i = 0; i < MT; i++) mma16816(acc_l[i][2 * jp],     a[i], b[0], b[1]);
#pragma unroll
                for (int i = 0; i < MT; i++) mma16816(acc_l[i][2 * jp + 1], a[i], b[2], b[3]);
            }
        }
        __syncthreads();
    }

    // epilogue: C = acc_hi + acc_lo/1024 + bias  (plain stores: keep C hot in L2
    // for the downstream LIF consumer — streaming hints measurably regressed)
    const int grp = lane >> 2, q = lane & 3;
#pragma unroll
    for (int i = 0; i < MT; i++) {
#pragma unroll
        for (int j = 0; j < NT; j++) {
            int row0 = bm0 + wm0 + i * 16 + grp;
            int row1 = row0 + 8;
            int col  = bn0 + wn0 + j * 8 + q * 2;
            float bv0 = bias[col];
            float bv1 = bias[col + 1];
            float v00 = fmaf(acc_l[i][j][0], LO_INV_SCALE, acc_h[i][j][0]) + bv0;
            float v01 = fmaf(acc_l[i][j][1], LO_INV_SCALE, acc_h[i][j][1]) + bv1;
            float v10 = fmaf(acc_l[i][j][2], LO_INV_SCALE, acc_h[i][j][2]) + bv0;
            float v11 = fmaf(acc_l[i][j][3], LO_INV_SCALE, acc_h[i][j][3]) + bv1;
            *(float2*)&C[(size_t)row0 * N + col] = make_float2(v00, v01);
            *(float2*)&C[(size_t)row1 * N + col] = make_float2(v10, v11);
        }
    }
}

// ======================= LIF layer 1: currents -> spikes (fp16) =======================
// mem_t = 0.9*mem + cur_t - spk_{t-1};  spk_t = (mem_t - 1 > 0). _rn ops forbid FMA fusion.
__global__ void lif1_kernel(const float* __restrict__ cur, __half* __restrict__ spk) {
    int idx = blockIdx.x * blockDim.x + threadIdx.x;   // = b*HID + h
    if (idx >= BATCH * HID_DIM) return;
    float mem = 0.f, sp = 0.f;
#pragma unroll
    for (int t = 0; t < T_STEPS; t++) {
        float c = cur[(size_t)t * BATCH * HID_DIM + idx];
        mem = __fsub_rn(__fadd_rn(__fmul_rn(0.9f, mem), c), sp);
        sp  = (mem > 1.0f) ? 1.f : 0.f;
        spk[(size_t)t * BATCH * HID_DIM + idx] = __float2half_rn(sp);
    }
}

// ======================= LIF layer 2: currents -> spike counts =======================
__global__ void lif2_kernel(const float* __restrict__ cur, float* __restrict__ out) {
    int idx = blockIdx.x * blockDim.x + threadIdx.x;   // = b*OUT + o
    if (idx >= BATCH * OUT_DIM) return;
    float mem = 0.f, sp = 0.f, cnt = 0.f;
#pragma unroll
    for (int t = 0; t < T_STEPS; t++) {
        float c = cur[(size_t)t * BATCH * OUT_DIM + idx];
        mem = __fsub_rn(__fadd_rn(__fmul_rn(0.9f, mem), c), sp);
        sp  = (mem > 1.0f) ? 1.f : 0.f;
        cnt += sp;
    }
    out[idx] = cnt;
}

// ======================= launch =======================
extern "C" void kernel_launch(void* const* d_in, const int* in_sizes, int n_in,
                              void* d_out, int out_size) {
    const float* x  = (const float*)d_in[0];   // [25,1024,1024]
    const float* w1 = (const float*)d_in[1];   // [4096,1024]
    const float* b1 = (const float*)d_in[2];   // [4096]
    const float* w2 = (const float*)d_in[3];   // [64,4096]
    const float* b2 = (const float*)d_in[4];   // [64]
    float* out = (float*)d_out;                // [1024,64]

    __half *A, *w1hi, *w1lo, *w2hi, *w2lo, *spk1;
    float *cur1, *cur2;
    cudaGetSymbolAddress((void**)&A,    g_A);
    cudaGetSymbolAddress((void**)&w1hi, g_w1hi);
    cudaGetSymbolAddress((void**)&w1lo, g_w1lo);
    cudaGetSymbolAddress((void**)&w2hi, g_w2hi);
    cudaGetSymbolAddress((void**)&w2lo, g_w2lo);
    cudaGetSymbolAddress((void**)&spk1, g_spk1);
    cudaGetSymbolAddress((void**)&cur1, g_cur1);
    cudaGetSymbolAddress((void**)&cur2, g_cur2);

    // GEMM1 (round-5 optimum): BM=128,BN=64,WM=32,WN=32 -> 8 warps, 2 CTAs/SM.
    constexpr int SMEM1 = 2 * (128 * 72 + 2 * 64 * 72) * 2;   // 73728 B
    // GEMM2: BM=64,BN=64,WM=32,WN=16 -> 8 warps, grid 1x400 (one balanced wave).
    constexpr int SMEM2 = 2 * (64 * 72 + 2 * 64 * 72) * 2;    // 55296 B
    cudaFuncSetAttribute((const void*)gemm_hilo<128, 64, 64, 32, 32, 2>,
                         cudaFuncAttributeMaxDynamicSharedMemorySize, SMEM1);
    cudaFuncSetAttribute((const void*)gemm_hilo<64, 64, 64, 32, 16, 2>,
                         cudaFuncAttributeMaxDynamicSharedMemorySize, SMEM2);

    // 1) prep
    k_cvt_spikes<<<4096, 256>>>(x, A, M_ROWS * IN_DIM);
    k_split<<<2048, 256>>>(w1, w1hi, w1lo, HID_DIM * IN_DIM);
    k_split<<<512, 256>>>(w2, w2hi, w2lo, OUT_DIM * HID_DIM);

    // 2) GEMM1: cur1[25600,4096] = A[25600,1024] @ w1^T + b1  (grid 64x200)
    gemm_hilo<128, 64, 64, 32, 32, 2>
        <<<dim3(HID_DIM / 64, M_ROWS / 128), 256, SMEM1>>>(
            A, w1hi, w1lo, b1, cur1, M_ROWS, HID_DIM, IN_DIM);

    // 3) LIF layer 1
    lif1_kernel<<<(BATCH * HID_DIM) / 256, 256>>>(cur1, spk1);

    // 4) GEMM2: cur2[25600,64] = spk1 @ w2^T + b2  (grid 1x400, all CTAs resident)
    gemm_hilo<64, 64, 64, 32, 16, 2>
        <<<dim3(OUT_DIM / 64, M_ROWS / 64), 256, SMEM2>>>(
            spk1, w2hi, w2lo, b2, cur2, M_ROWS, OUT_DIM, HID_DIM);

    // 5) LIF layer 2 + spike counting
    lif2_kernel<<<(BATCH * OUT_DIM) / 256, 256>>>(cur2, out);
}

// round 12
// speedup vs baseline: 1.2779x; 1.0141x over previous
#include <cuda_runtime.h>
#include <cuda_fp16.h>
#include <cstdint>
#include <cstddef>

// ======================= problem dims (fixed) =======================
#define T_STEPS 25
#define BATCH   1024
#define IN_DIM  1024
#define HID_DIM 4096
#define OUT_DIM 64
#define M_ROWS  (T_STEPS * BATCH)   // 25600
#define HIDW    (HID_DIM / 32)      // 128 bit-words per row

#define LO_SCALE     1024.0f
#define LO_INV_SCALE 0.0009765625f  // exact 2^-10

// ======================= static device scratch =======================
__device__ __half   g_A    [(size_t)M_ROWS * IN_DIM];     // fp16 input spikes (exact 0/1)
__device__ __half   g_w1hi [(size_t)HID_DIM * IN_DIM];
__device__ __half   g_w1lo [(size_t)HID_DIM * IN_DIM];    // (w - hi) * 1024, fp16-normal
__device__ __half   g_w2hi [(size_t)OUT_DIM * HID_DIM];
__device__ __half   g_w2lo [(size_t)OUT_DIM * HID_DIM];
__device__ float    g_cur1 [(size_t)M_ROWS * HID_DIM];    // layer-1 currents
__device__ uint32_t g_spkb [(size_t)M_ROWS * HIDW];       // layer-1 spikes, bit-packed (13 MB)
__device__ float    g_cur2 [(size_t)M_ROWS * OUT_DIM];    // layer-2 currents

// ======================= helpers =======================
__device__ __forceinline__ void cp16(void* dst_smem, const void* src_gmem) {
    uint32_t d = (uint32_t)__cvta_generic_to_shared(dst_smem);
    asm volatile("cp.async.cg.shared.global [%0], [%1], 16;" :: "r"(d), "l"(src_gmem));
}
__device__ __forceinline__ void cp_commit() { asm volatile("cp.async.commit_group;"); }
__device__ __forceinline__ void cp_wait1()  { asm volatile("cp.async.wait_group 1;"); }
__device__ __forceinline__ void cp_wait0()  { asm volatile("cp.async.wait_group 0;"); }

__device__ __forceinline__ void ldsm_x4(uint32_t* r, uint32_t saddr) {
    asm volatile("ldmatrix.sync.aligned.m8n8.x4.shared.b16 {%0,%1,%2,%3}, [%4];"
        : "=r"(r[0]), "=r"(r[1]), "=r"(r[2]), "=r"(r[3]) : "r"(saddr));
}

__device__ __forceinline__ void mma16816(float* c, const uint32_t* a, uint32_t b0, uint32_t b1) {
    asm volatile(
        "mma.sync.aligned.m16n8k16.row.col.f32.f16.f16.f32 "
        "{%0,%1,%2,%3}, {%4,%5,%6,%7}, {%8,%9}, {%0,%1,%2,%3};"
        : "+f"(c[0]), "+f"(c[1]), "+f"(c[2]), "+f"(c[3])
        : "r"(a[0]), "r"(a[1]), "r"(a[2]), "r"(a[3]), "r"(b0), "r"(b1));
}

// ======================= prep kernels =======================
__global__ void k_cvt_spikes(const float* __restrict__ x, __half* __restrict__ y, int n) {
    for (int i = blockIdx.x * blockDim.x + threadIdx.x; i < n; i += gridDim.x * blockDim.x)
        y[i] = __float2half_rn(x[i]);   // 0.0 / 1.0 -> exact fp16
}

__global__ void k_split(const float* __restrict__ w, __half* __restrict__ hi,
                        __half* __restrict__ lo, int n) {
    for (int i = blockIdx.x * blockDim.x + threadIdx.x; i < n; i += gridDim.x * blockDim.x) {
        float v = w[i];
        __half h = __float2half_rn(v);
        hi[i] = h;
        // residual scaled into fp16-normal range; own accumulator keeps planes
        // scale-homogeneous (tensor-core accum truncates tiny addends vs big C).
        lo[i] = __float2half_rn(__fmul_rn(__fsub_rn(v, __half2float(h)), LO_SCALE));
    }
}

// ====== GEMM1: C[M,N] = A[M,K] @ (Whi + Wlo/1024)[N,K]^T + bias (two-plane accum) ======
// FROZEN round-5 optimum. 2-stage cp.async; ldmatrix.x4; separate fp32 accumulators
// per plane, combined as acc_hi + acc_lo/1024 + bias in the epilogue.
template <int BM, int BN, int BK, int WM, int WN, int MINCTA>
__global__ void __launch_bounds__((BM / WM) * (BN / WN) * 32, MINCTA)
gemm_hilo(const __half* __restrict__ A,
          const __half* __restrict__ Whi,
          const __half* __restrict__ Wlo,
          const float* __restrict__ bias,
          float* __restrict__ C,
          int M, int N, int K)
{
    constexpr int BKP  = BK + 8;
    constexpr int NW   = (BM / WM) * (BN / WN);
    constexpr int NTH  = NW * 32;
    constexpr int MT   = WM / 16;
    constexpr int NT   = WN / 8;
    constexpr int KCH  = BK / 8;
    constexpr int ACH  = BM * KCH;
    constexpr int BCH  = BN * KCH;

    extern __shared__ __align__(16) unsigned char smem_raw[];
    __half* As = reinterpret_cast<__half*>(smem_raw);   // [2][BM][BKP]
    __half* Bs = As + 2 * BM * BKP;                      // [2][2][BN][BKP]

    const int tid  = threadIdx.x;
    const int wid  = tid >> 5;
    const int lane = tid & 31;

    const int wm0 = (wid % (BM / WM)) * WM;
    const int wn0 = (wid / (BM / WM)) * WN;
    const int bm0 = blockIdx.y * BM;
    const int bn0 = blockIdx.x * BN;
    const int NK  = K / BK;

    const int mi = lane >> 3, rr = lane & 7;
    const int a_roff = (mi & 1) * 8 + rr;
    const int a_coff = (mi >> 1) * 8;
    const int b_roff = (mi >> 1) * 8 + rr;
    const int b_coff = (mi & 1) * 8;

    const uint32_t as_u = (uint32_t)__cvta_generic_to_shared(As);
    const uint32_t bs_u = (uint32_t)__cvta_generic_to_shared(Bs);

    float acc_h[MT][NT][4];
    float acc_l[MT][NT][4];
#pragma unroll
    for (int i = 0; i < MT; i++)
#pragma unroll
        for (int j = 0; j < NT; j++)
#pragma unroll
            for (int e = 0; e < 4; e++) { acc_h[i][j][e] = 0.f; acc_l[i][j][e] = 0.f; }

    auto load_stage = [&](int stage, int kt) {
        const int k0 = kt * BK;
#pragma unroll
        for (int c = tid; c < ACH; c += NTH) {
            int row = c / KCH, kc = (c % KCH) * 8;
            cp16(&As[(stage * BM + row) * BKP + kc],
                 A + (size_t)(bm0 + row) * K + k0 + kc);
        }
#pragma unroll
        for (int c = tid; c < BCH; c += NTH) {
            int row = c / KCH, kc = (c % KCH) * 8;
            size_t g = (size_t)(bn0 + row) * K + k0 + kc;
            cp16(&Bs[((stage * 2 + 0) * BN + row) * BKP + kc], Whi + g);
            cp16(&Bs[((stage * 2 + 1) * BN + row) * BKP + kc], Wlo + g);
        }
    };

    load_stage(0, 0);
    cp_commit();

    for (int kt = 0; kt < NK; kt++) {
        const int buf = kt & 1;
        if (kt + 1 < NK) {
            load_stage(buf ^ 1, kt + 1);
            cp_commit();
            cp_wait1();
        } else {
            cp_wait0();
        }
        __syncthreads();

#pragma unroll
        for (int kk = 0; kk < BK / 16; kk++) {
            uint32_t a[MT][4];
#pragma unroll
            for (int i = 0; i < MT; i++)
                ldsm_x4(a[i], as_u +
                    (uint32_t)(((buf * BM + wm0 + i * 16 + a_roff) * BKP
                                + kk * 16 + a_coff) * 2));
#pragma unroll
            for (int jp = 0; jp < NT / 2; jp++) {
                uint32_t b[4];
                ldsm_x4(b, bs_u +
                    (uint32_t)((((buf * 2 + 0) * BN + wn0 + jp * 16 + b_roff) * BKP
                                + kk * 16 + b_coff) * 2));
#pragma unroll
                for (int i = 0; i < MT; i++) mma16816(acc_h[i][2 * jp],     a[i], b[0], b[1]);
#pragma unroll
                for (int i = 0; i < MT; i++) mma16816(acc_h[i][2 * jp + 1], a[i], b[2], b[3]);
            }
#pragma unroll
            for (int jp = 0; jp < NT / 2; jp++) {
                uint32_t b[4];
                ldsm_x4(b, bs_u +
                    (uint32_t)((((buf * 2 + 1) * BN + wn0 + jp * 16 + b_roff) * BKP
                                + kk * 16 + b_coff) * 2));
#pragma unroll
                for (int i = 0; i < MT; i++) mma16816(acc_l[i][2 * jp],     a[i], b[0], b[1]);
#pragma unroll
                for (int i = 0; i < MT; i++) mma16816(acc_l[i][2 * jp + 1], a[i], b[2], b[3]);
            }
        }
        __syncthreads();
    }

    const int grp = lane >> 2, q = lane & 3;
#pragma unroll
    for (int i = 0; i < MT; i++) {
#pragma unroll
        for (int j = 0; j < NT; j++) {
            int row0 = bm0 + wm0 + i * 16 + grp;
            int row1 = row0 + 8;
            int col  = bn0 + wn0 + j * 8 + q * 2;
            float bv0 = bias[col];
            float bv1 = bias[col + 1];
            float v00 = fmaf(acc_l[i][j][0], LO_INV_SCALE, acc_h[i][j][0]) + bv0;
            float v01 = fmaf(acc_l[i][j][1], LO_INV_SCALE, acc_h[i][j][1]) + bv1;
            float v10 = fmaf(acc_l[i][j][2], LO_INV_SCALE, acc_h[i][j][2]) + bv0;
            float v11 = fmaf(acc_l[i][j][3], LO_INV_SCALE, acc_h[i][j][3]) + bv1;
            *(float2*)&C[(size_t)row0 * N + col] = make_float2(v00, v01);
            *(float2*)&C[(size_t)row1 * N + col] = make_float2(v10, v11);
        }
    }
}

// ====== GEMM2 (bit-packed A): C[M,64] = spikes[M,K] @ (Whi + Wlo/1024)^T + bias ======
// BM=64, BN=64, BK=64, WM=32, WN=16, 8 warps. A arrives as 1 bit/value; staging
// expands bits -> fp16 {0, 1.0} (exact) with ALU bit-spread; B via cp.async.
#define G2_BM 64
#define G2_BK 64
#define G2_BKP 72
__global__ void __launch_bounds__(256, 2)
gemm2_bits(const uint32_t* __restrict__ Abits,
           const __half* __restrict__ Whi,
           const __half* __restrict__ Wlo,
           const float* __restrict__ bias,
           float* __restrict__ C,
           int M, int N, int K)
{
    constexpr int BM = G2_BM, BN = 64, BK = G2_BK, BKP = G2_BKP;
    constexpr int MT = 2, NT = 2;               // WM=32, WN=16
    constexpr int KCH = BK / 8;                 // 8
    constexpr int BCH = BN * KCH;               // 512

    extern __shared__ __align__(16) unsigned char smem_raw[];
    __half* As = reinterpret_cast<__half*>(smem_raw);   // [2][BM][BKP]
    __half* Bs = As + 2 * BM * BKP;                      // [2][2][BN][BKP]

    const int tid  = threadIdx.x;
    const int wid  = tid >> 5;
    const int lane = tid & 31;

    const int wm0 = (wid & 1) * 32;             // 2 warps along M
    const int wn0 = (wid >> 1) * 16;            // 4 warps along N
    const int bm0 = blockIdx.y * BM;
    const int NK  = K / BK;
    const int KW  = K >> 5;                     // bit-words per row

    const int mi = lane >> 3, rr = lane & 7;
    const int a_roff = (mi & 1) * 8 + rr;
    const int a_coff = (mi >> 1) * 8;
    const int b_roff = (mi >> 1) * 8 + rr;
    const int b_coff = (mi & 1) * 8;

    const uint32_t as_u = (uint32_t)__cvta_generic_to_shared(As);
    const uint32_t bs_u = (uint32_t)__cvta_generic_to_shared(Bs);

    float acc_h[MT][NT][4];
    float acc_l[MT][NT][4];
#pragma unroll
    for (int i = 0; i < MT; i++)
#pragma unroll
        for (int j = 0; j < NT; j++)
#pragma unroll
            for (int e = 0; e < 4; e++) { acc_h[i][j][e] = 0.f; acc_l[i][j][e] = 0.f; }

    auto load_stage = [&](int stage, int kt) {
        const int k0 = kt * BK;
        // A: 64 rows x 64 bits = 128 words; threads 0..127 expand 32 values each
        if (tid < 128) {
            int row = tid >> 1, half = tid & 1;
            uint32_t w = Abits[(size_t)(bm0 + row) * KW + (kt << 1) + half];
            __half* dst = &As[(stage * BM + row) * BKP + half * 32];
#pragma unroll
            for (int g = 0; g < 8; g++) {
                uint32_t b4 = w >> (4 * g);
                uint32_t lo = ((b4 & 1) * 0x3C00u) | (((b4 >> 1) & 1) * 0x3C000000u);
                uint32_t hi = (((b4 >> 2) & 1) * 0x3C00u) | (((b4 >> 3) & 1) * 0x3C000000u);
                *(uint2*)(dst + g * 4) = make_uint2(lo, hi);   // 8B-aligned (144B rows)
            }
        }
        // B hi/lo planes via cp.async
#pragma unroll
        for (int c = tid; c < BCH; c += 256) {
            int row = c / KCH, kc = (c % KCH) * 8;
            size_t g = (size_t)row * K + k0 + kc;
            cp16(&Bs[((stage * 2 + 0) * BN + row) * BKP + kc], Whi + g);
            cp16(&Bs[((stage * 2 + 1) * BN + row) * BKP + kc], Wlo + g);
        }
    };

    load_stage(0, 0);
    cp_commit();

    for (int kt = 0; kt < NK; kt++) {
        const int buf = kt & 1;
        if (kt + 1 < NK) {
            load_stage(buf ^ 1, kt + 1);
            cp_commit();
            cp_wait1();
        } else {
            cp_wait0();
        }
        __syncthreads();

#pragma unroll
        for (int kk = 0; kk < BK / 16; kk++) {
            uint32_t a[MT][4];
#pragma unroll
            for (int i = 0; i < MT; i++)
                ldsm_x4(a[i], as_u +
                    (uint32_t)(((buf * BM + wm0 + i * 16 + a_roff) * BKP
                                + kk * 16 + a_coff) * 2));
            {
                uint32_t b[4];
                ldsm_x4(b, bs_u +
                    (uint32_t)((((buf * 2 + 0) * BN + wn0 + b_roff) * BKP
                                + kk * 16 + b_coff) * 2));
#pragma unroll
                for (int i = 0; i < MT; i++) mma16816(acc_h[i][0], a[i], b[0], b[1]);
#pragma unroll
                for (int i = 0; i < MT; i++) mma16816(acc_h[i][1], a[i], b[2], b[3]);
            }
            {
                uint32_t b[4];
                ldsm_x4(b, bs_u +
                    (uint32_t)((((buf * 2 + 1) * BN + wn0 + b_roff) * BKP
                                + kk * 16 + b_coff) * 2));
#pragma unroll
                for (int i = 0; i < MT; i++) mma16816(acc_l[i][0], a[i], b[0], b[1]);
#pragma unroll
                for (int i = 0; i < MT; i++) mma16816(acc_l[i][1], a[i], b[2], b[3]);
            }
        }
        __syncthreads();
    }

    const int grp = lane >> 2, q = lane & 3;
#pragma unroll
    for (int i = 0; i < MT; i++) {
#pragma unroll
        for (int j = 0; j < NT; j++) {
            int row0 = bm0 + wm0 + i * 16 + grp;
            int row1 = row0 + 8;
            int col  = wn0 + j * 8 + q * 2;
            float bv0 = bias[col];
            float bv1 = bias[col + 1];
            float v00 = fmaf(acc_l[i][j][0], LO_INV_SCALE, acc_h[i][j][0]) + bv0;
            float v01 = fmaf(acc_l[i][j][1], LO_INV_SCALE, acc_h[i][j][1]) + bv1;
            float v10 = fmaf(acc_l[i][j][2], LO_INV_SCALE, acc_h[i][j][2]) + bv0;
            float v11 = fmaf(acc_l[i][j][3], LO_INV_SCALE, acc_h[i][j][3]) + bv1;
            *(float2*)&C[(size_t)row0 * N + col] = make_float2(v00, v01);
            *(float2*)&C[(size_t)row1 * N + col] = make_float2(v10, v11);
        }
    }
}

// ======================= LIF layer 1: currents -> bit-packed spikes =======================
// mem_t = 0.9*mem + cur_t - spk_{t-1};  spk_t = (mem_t - 1 > 0). _rn ops forbid FMA fusion.
// Warp = 32 consecutive h of one b -> ballot packs 32 spike bits per STG.32.
__global__ void lif1_kernel(const float* __restrict__ cur, uint32_t* __restrict__ spkb) {
    int idx = blockIdx.x * blockDim.x + threadIdx.x;   // = b*HID + h
    int b = idx >> 12;                                  // HID_DIM = 4096
    int h = idx & (HID_DIM - 1);
    int lane = threadIdx.x & 31;
    float mem = 0.f, sp = 0.f;
#pragma unroll
    for (int t = 0; t < T_STEPS; t++) {
        float c = cur[(size_t)t * BATCH * HID_DIM + idx];
        mem = __fsub_rn(__fadd_rn(__fmul_rn(0.9f, mem), c), sp);
        sp  = (mem > 1.0f) ? 1.f : 0.f;
        uint32_t bits = __ballot_sync(0xFFFFFFFFu, mem > 1.0f);
        if (lane == 0)
            spkb[(size_t)(t * BATCH + b) * HIDW + (h >> 5)] = bits;
    }
}

// ======================= LIF layer 2: currents -> spike counts =======================
__global__ void lif2_kernel(const float* __restrict__ cur, float* __restrict__ out) {
    int idx = blockIdx.x * blockDim.x + threadIdx.x;   // = b*OUT + o
    if (idx >= BATCH * OUT_DIM) return;
    float mem = 0.f, sp = 0.f, cnt = 0.f;
#pragma unroll
    for (int t = 0; t < T_STEPS; t++) {
        float c = cur[(size_t)t * BATCH * OUT_DIM + idx];
        mem = __fsub_rn(__fadd_rn(__fmul_rn(0.9f, mem), c), sp);
        sp  = (mem > 1.0f) ? 1.f : 0.f;
        cnt += sp;
    }
    out[idx] = cnt;
}

// ======================= launch =======================
extern "C" void kernel_launch(void* const* d_in, const int* in_sizes, int n_in,
                              void* d_out, int out_size) {
    const float* x  = (const float*)d_in[0];   // [25,1024,1024]
    const float* w1 = (const float*)d_in[1];   // [4096,1024]
    const float* b1 = (const float*)d_in[2];   // [4096]
    const float* w2 = (const float*)d_in[3];   // [64,4096]
    const float* b2 = (const float*)d_in[4];   // [64]
    float* out = (float*)d_out;                // [1024,64]

    __half *A, *w1hi, *w1lo, *w2hi, *w2lo;
    uint32_t* spkb;
    float *cur1, *cur2;
    cudaGetSymbolAddress((void**)&A,    g_A);
    cudaGetSymbolAddress((void**)&w1hi, g_w1hi);
    cudaGetSymbolAddress((void**)&w1lo, g_w1lo);
    cudaGetSymbolAddress((void**)&w2hi, g_w2hi);
    cudaGetSymbolAddress((void**)&w2lo, g_w2lo);
    cudaGetSymbolAddress((void**)&spkb, g_spkb);
    cudaGetSymbolAddress((void**)&cur1, g_cur1);
    cudaGetSymbolAddress((void**)&cur2, g_cur2);

    // GEMM1 (frozen optimum): BM=128,BN=64,WM=32,WN=32 -> 8 warps, 2 CTAs/SM.
    constexpr int SMEM1 = 2 * (128 * 72 + 2 * 64 * 72) * 2;   // 73728 B
    // GEMM2 bits: [2][64][72] A + [2][2][64][72] B halves * 2B = 55296 B
    constexpr int SMEM2 = 2 * (64 * 72 + 2 * 64 * 72) * 2;
    cudaFuncSetAttribute((const void*)gemm_hilo<128, 64, 64, 32, 32, 2>,
                         cudaFuncAttributeMaxDynamicSharedMemorySize, SMEM1);
    cudaFuncSetAttribute((const void*)gemm2_bits,
                         cudaFuncAttributeMaxDynamicSharedMemorySize, SMEM2);

    // 1) prep
    k_cvt_spikes<<<4096, 256>>>(x, A, M_ROWS * IN_DIM);
    k_split<<<2048, 256>>>(w1, w1hi, w1lo, HID_DIM * IN_DIM);
    k_split<<<512, 256>>>(w2, w2hi, w2lo, OUT_DIM * HID_DIM);

    // 2) GEMM1: cur1[25600,4096] = A[25600,1024] @ w1^T + b1  (grid 64x200)
    gemm_hilo<128, 64, 64, 32, 32, 2>
        <<<dim3(HID_DIM / 64, M_ROWS / 128), 256, SMEM1>>>(
            A, w1hi, w1lo, b1, cur1, M_ROWS, HID_DIM, IN_DIM);

    // 3) LIF layer 1 -> bit-packed spikes
    lif1_kernel<<<(BATCH * HID_DIM) / 256, 256>>>(cur1, spkb);

    // 4) GEMM2: cur2[25600,64] = spikes @ w2^T + b2  (grid 1x400, bit-expand A)
    gemm2_bits<<<dim3(1, M_ROWS / G2_BM), 256, SMEM2>>>(
        spkb, w2hi, w2lo, b2, cur2, M_ROWS, OUT_DIM, HID_DIM);

    // 5) LIF layer 2 + spike counting
    lif2_kernel<<<(BATCH * OUT_DIM) / 256, 256>>>(cur2, out);
}

// round 13
// speedup vs baseline: 1.2957x; 1.0139x over previous
#include <cuda_runtime.h>
#include <cuda_fp16.h>
#include <cstdint>
#include <cstddef>

// ======================= problem dims (fixed) =======================
#define T_STEPS 25
#define BATCH   1024
#define IN_DIM  1024
#define HID_DIM 4096
#define OUT_DIM 64
#define M_ROWS  (T_STEPS * BATCH)   // 25600
#define HIDW    (HID_DIM / 32)      // 128 bit-words per row

#define LO_SCALE     1024.0f
#define LO_INV_SCALE 0.0009765625f  // exact 2^-10

// ======================= static device scratch =======================
__device__ __half   g_A    [(size_t)M_ROWS * IN_DIM];     // fp16 input spikes (exact 0/1)
__device__ __half   g_w1hi [(size_t)HID_DIM * IN_DIM];
__device__ __half   g_w1lo [(size_t)HID_DIM * IN_DIM];    // (w - hi) * 1024, fp16-normal
__device__ __half   g_w2hi [(size_t)OUT_DIM * HID_DIM];
__device__ __half   g_w2lo [(size_t)OUT_DIM * HID_DIM];
__device__ float    g_cur1 [(size_t)M_ROWS * HID_DIM];    // layer-1 currents
__device__ uint32_t g_spkb [(size_t)M_ROWS * HIDW];       // layer-1 spikes, bit-packed
__device__ float    g_cur2 [(size_t)M_ROWS * OUT_DIM];    // layer-2 currents

// ======================= helpers =======================
__device__ __forceinline__ void cp16(void* dst_smem, const void* src_gmem) {
    uint32_t d = (uint32_t)__cvta_generic_to_shared(dst_smem);
    asm volatile("cp.async.cg.shared.global [%0], [%1], 16;" :: "r"(d), "l"(src_gmem));
}
__device__ __forceinline__ void cp_commit() { asm volatile("cp.async.commit_group;"); }
__device__ __forceinline__ void cp_wait1()  { asm volatile("cp.async.wait_group 1;"); }
__device__ __forceinline__ void cp_wait0()  { asm volatile("cp.async.wait_group 0;"); }

__device__ __forceinline__ void ldsm_x4(uint32_t* r, uint32_t saddr) {
    asm volatile("ldmatrix.sync.aligned.m8n8.x4.shared.b16 {%0,%1,%2,%3}, [%4];"
        : "=r"(r[0]), "=r"(r[1]), "=r"(r[2]), "=r"(r[3]) : "r"(saddr));
}

__device__ __forceinline__ void mma16816(float* c, const uint32_t* a, uint32_t b0, uint32_t b1) {
    asm volatile(
        "mma.sync.aligned.m16n8k16.row.col.f32.f16.f16.f32 "
        "{%0,%1,%2,%3}, {%4,%5,%6,%7}, {%8,%9}, {%0,%1,%2,%3};"
        : "+f"(c[0]), "+f"(c[1]), "+f"(c[2]), "+f"(c[3])
        : "r"(a[0]), "r"(a[1]), "r"(a[2]), "r"(a[3]), "r"(b0), "r"(b1));
}

// ======================= merged prep kernel =======================
// Segment 1: cvt input spikes fp32 -> fp16 (exact 0/1)
// Segment 2: split w1 -> hi/lo planes     Segment 3: split w2 -> hi/lo planes
#define N_CVT (M_ROWS * IN_DIM)       // 26214400
#define N_W1  (HID_DIM * IN_DIM)      // 4194304
#define N_W2  (OUT_DIM * HID_DIM)     // 262144
__global__ void k_prep(const float* __restrict__ x, __half* __restrict__ A,
                       const float* __restrict__ w1, __half* __restrict__ w1hi,
                       __half* __restrict__ w1lo,
                       const float* __restrict__ w2, __half* __restrict__ w2hi,
                       __half* __restrict__ w2lo) {
    const int total = N_CVT + N_W1 + N_W2;
    for (int i = blockIdx.x * blockDim.x + threadIdx.x; i < total;
         i += gridDim.x * blockDim.x) {
        if (i < N_CVT) {
            A[i] = __float2half_rn(x[i]);
        } else {
            const float* w; __half *hi, *lo; int j;
            if (i < N_CVT + N_W1) { j = i - N_CVT; w = w1; hi = w1hi; lo = w1lo; }
            else                  { j = i - N_CVT - N_W1; w = w2; hi = w2hi; lo = w2lo; }
            float v = w[j];
            __half h = __float2half_rn(v);
            hi[j] = h;
            // residual scaled into fp16-normal range; own accumulator downstream
            // keeps planes scale-homogeneous (exactness of products preserved).
            lo[j] = __float2half_rn(__fmul_rn(__fsub_rn(v, __half2float(h)), LO_SCALE));
        }
    }
}

// ====== GEMM1: C[M,N] = A[M,K] @ (Whi + Wlo/1024)[N,K]^T + bias (two-plane accum) ======
// FROZEN optimum (round 5). 2-stage cp.async; ldmatrix.x4; separate fp32 accumulators
// per plane, combined as acc_hi + acc_lo/1024 + bias in the epilogue.
template <int BM, int BN, int BK, int WM, int WN, int MINCTA>
__global__ void __launch_bounds__((BM / WM) * (BN / WN) * 32, MINCTA)
gemm_hilo(const __half* __restrict__ A,
          const __half* __restrict__ Whi,
          const __half* __restrict__ Wlo,
          const float* __restrict__ bias,
          float* __restrict__ C,
          int M, int N, int K)
{
    constexpr int BKP  = BK + 8;
    constexpr int NW   = (BM / WM) * (BN / WN);
    constexpr int NTH  = NW * 32;
    constexpr int MT   = WM / 16;
    constexpr int NT   = WN / 8;
    constexpr int KCH  = BK / 8;
    constexpr int ACH  = BM * KCH;
    constexpr int BCH  = BN * KCH;

    extern __shared__ __align__(16) unsigned char smem_raw[];
    __half* As = reinterpret_cast<__half*>(smem_raw);   // [2][BM][BKP]
    __half* Bs = As + 2 * BM * BKP;                      // [2][2][BN][BKP]

    const int tid  = threadIdx.x;
    const int wid  = tid >> 5;
    const int lane = tid & 31;

    const int wm0 = (wid % (BM / WM)) * WM;
    const int wn0 = (wid / (BM / WM)) * WN;
    const int bm0 = blockIdx.y * BM;
    const int bn0 = blockIdx.x * BN;
    const int NK  = K / BK;

    const int mi = lane >> 3, rr = lane & 7;
    const int a_roff = (mi & 1) * 8 + rr;
    const int a_coff = (mi >> 1) * 8;
    const int b_roff = (mi >> 1) * 8 + rr;
    const int b_coff = (mi & 1) * 8;

    const uint32_t as_u = (uint32_t)__cvta_generic_to_shared(As);
    const uint32_t bs_u = (uint32_t)__cvta_generic_to_shared(Bs);

    float acc_h[MT][NT][4];
    float acc_l[MT][NT][4];
#pragma unroll
    for (int i = 0; i < MT; i++)
#pragma unroll
        for (int j = 0; j < NT; j++)
#pragma unroll
            for (int e = 0; e < 4; e++) { acc_h[i][j][e] = 0.f; acc_l[i][j][e] = 0.f; }

    auto load_stage = [&](int stage, int kt) {
        const int k0 = kt * BK;
#pragma unroll
        for (int c = tid; c < ACH; c += NTH) {
            int row = c / KCH, kc = (c % KCH) * 8;
            cp16(&As[(stage * BM + row) * BKP + kc],
                 A + (size_t)(bm0 + row) * K + k0 + kc);
        }
#pragma unroll
        for (int c = tid; c < BCH; c += NTH) {
            int row = c / KCH, kc = (c % KCH) * 8;
            size_t g = (size_t)(bn0 + row) * K + k0 + kc;
            cp16(&Bs[((stage * 2 + 0) * BN + row) * BKP + kc], Whi + g);
            cp16(&Bs[((stage * 2 + 1) * BN + row) * BKP + kc], Wlo + g);
        }
    };

    load_stage(0, 0);
    cp_commit();

    for (int kt = 0; kt < NK; kt++) {
        const int buf = kt & 1;
        if (kt + 1 < NK) {
            load_stage(buf ^ 1, kt + 1);
            cp_commit();
            cp_wait1();
        } else {
            cp_wait0();
        }
        __syncthreads();

#pragma unroll
        for (int kk = 0; kk < BK / 16; kk++) {
            uint32_t a[MT][4];
#pragma unroll
            for (int i = 0; i < MT; i++)
                ldsm_x4(a[i], as_u +
                    (uint32_t)(((buf * BM + wm0 + i * 16 + a_roff) * BKP
                                + kk * 16 + a_coff) * 2));
#pragma unroll
            for (int jp = 0; jp < NT / 2; jp++) {
                uint32_t b[4];
                ldsm_x4(b, bs_u +
                    (uint32_t)((((buf * 2 + 0) * BN + wn0 + jp * 16 + b_roff) * BKP
                                + kk * 16 + b_coff) * 2));
#pragma unroll
                for (int i = 0; i < MT; i++) mma16816(acc_h[i][2 * jp],     a[i], b[0], b[1]);
#pragma unroll
                for (int i = 0; i < MT; i++) mma16816(acc_h[i][2 * jp + 1], a[i], b[2], b[3]);
            }
#pragma unroll
            for (int jp = 0; jp < NT / 2; jp++) {
                uint32_t b[4];
                ldsm_x4(b, bs_u +
                    (uint32_t)((((buf * 2 + 1) * BN + wn0 + jp * 16 + b_roff) * BKP
                                + kk * 16 + b_coff) * 2));
#pragma unroll
                for (int i = 0; i < MT; i++) mma16816(acc_l[i][2 * jp],     a[i], b[0], b[1]);
#pragma unroll
                for (int i = 0; i < MT; i++) mma16816(acc_l[i][2 * jp + 1], a[i], b[2], b[3]);
            }
        }
        __syncthreads();
    }

    const int grp = lane >> 2, q = lane & 3;
#pragma unroll
    for (int i = 0; i < MT; i++) {
#pragma unroll
        for (int j = 0; j < NT; j++) {
            int row0 = bm0 + wm0 + i * 16 + grp;
            int row1 = row0 + 8;
            int col  = bn0 + wn0 + j * 8 + q * 2;
            float bv0 = bias[col];
            float bv1 = bias[col + 1];
            float v00 = fmaf(acc_l[i][j][0], LO_INV_SCALE, acc_h[i][j][0]) + bv0;
            float v01 = fmaf(acc_l[i][j][1], LO_INV_SCALE, acc_h[i][j][1]) + bv1;
            float v10 = fmaf(acc_l[i][j][2], LO_INV_SCALE, acc_h[i][j][2]) + bv0;
            float v11 = fmaf(acc_l[i][j][3], LO_INV_SCALE, acc_h[i][j][3]) + bv1;
            *(float2*)&C[(size_t)row0 * N + col] = make_float2(v00, v01);
            *(float2*)&C[(size_t)row1 * N + col] = make_float2(v10, v11);
        }
    }
}

// ====== GEMM2 (bit-packed A): C[M,64] = spikes[M,K] @ (Whi + Wlo/1024)^T + bias ======
// BM=64, BN=64, BK=64, WM=32, WN=16, 8 warps; A expanded bits -> fp16 {0,1} (exact).
// 3 CTAs/SM -> grid 400 fits in ONE wave (444 slots).
#define G2_BM 64
#define G2_BK 64
#define G2_BKP 72
__global__ void __launch_bounds__(256, 3)
gemm2_bits(const uint32_t* __restrict__ Abits,
           const __half* __restrict__ Whi,
           const __half* __restrict__ Wlo,
           const float* __restrict__ bias,
           float* __restrict__ C,
           int M, int N, int K)
{
    constexpr int BM = G2_BM, BN = 64, BK = G2_BK, BKP = G2_BKP;
    constexpr int MT = 2, NT = 2;               // WM=32, WN=16
    constexpr int KCH = BK / 8;                 // 8
    constexpr int BCH = BN * KCH;               // 512

    extern __shared__ __align__(16) unsigned char smem_raw[];
    __half* As = reinterpret_cast<__half*>(smem_raw);   // [2][BM][BKP]
    __half* Bs = As + 2 * BM * BKP;                      // [2][2][BN][BKP]

    const int tid  = threadIdx.x;
    const int wid  = tid >> 5;
    const int lane = tid & 31;

    const int wm0 = (wid & 1) * 32;             // 2 warps along M
    const int wn0 = (wid >> 1) * 16;            // 4 warps along N
    const int bm0 = blockIdx.y * BM;
    const int NK  = K / BK;
    const int KW  = K >> 5;                     // bit-words per row

    const int mi = lane >> 3, rr = lane & 7;
    const int a_roff = (mi & 1) * 8 + rr;
    const int a_coff = (mi >> 1) * 8;
    const int b_roff = (mi >> 1) * 8 + rr;
    const int b_coff = (mi & 1) * 8;

    const uint32_t as_u = (uint32_t)__cvta_generic_to_shared(As);
    const uint32_t bs_u = (uint32_t)__cvta_generic_to_shared(Bs);

    float acc_h[MT][NT][4];
    float acc_l[MT][NT][4];
#pragma unroll
    for (int i = 0; i < MT; i++)
#pragma unroll
        for (int j = 0; j < NT; j++)
#pragma unroll
            for (int e = 0; e < 4; e++) { acc_h[i][j][e] = 0.f; acc_l[i][j][e] = 0.f; }

    auto load_stage = [&](int stage, int kt) {
        const int k0 = kt * BK;
        // A: 64 rows x 64 bits = 128 words; threads 0..127 expand 32 values each
        if (tid < 128) {
            int row = tid >> 1, half = tid & 1;
            uint32_t w = Abits[(size_t)(bm0 + row) * KW + (kt << 1) + half];
            __half* dst = &As[(stage * BM + row) * BKP + half * 32];
#pragma unroll
            for (int g = 0; g < 8; g++) {
                uint32_t b4 = w >> (4 * g);
                uint32_t lo = ((b4 & 1) * 0x3C00u) | (((b4 >> 1) & 1) * 0x3C000000u);
                uint32_t hi = (((b4 >> 2) & 1) * 0x3C00u) | (((b4 >> 3) & 1) * 0x3C000000u);
                *(uint2*)(dst + g * 4) = make_uint2(lo, hi);
            }
        }
        // B hi/lo planes via cp.async
#pragma unroll
        for (int c = tid; c < BCH; c += 256) {
            int row = c / KCH, kc = (c % KCH) * 8;
            size_t g = (size_t)row * K + k0 + kc;
            cp16(&Bs[((stage * 2 + 0) * BN + row) * BKP + kc], Whi + g);
            cp16(&Bs[((stage * 2 + 1) * BN + row) * BKP + kc], Wlo + g);
        }
    };

    load_stage(0, 0);
    cp_commit();

    for (int kt = 0; kt < NK; kt++) {
        const int buf = kt & 1;
        if (kt + 1 < NK) {
            load_stage(buf ^ 1, kt + 1);
            cp_commit();
            cp_wait1();
        } else {
            cp_wait0();
        }
        __syncthreads();

#pragma unroll
        for (int kk = 0; kk < BK / 16; kk++) {
            uint32_t a[MT][4];
#pragma unroll
            for (int i = 0; i < MT; i++)
                ldsm_x4(a[i], as_u +
                    (uint32_t)(((buf * BM + wm0 + i * 16 + a_roff) * BKP
                                + kk * 16 + a_coff) * 2));
            {
                uint32_t b[4];
                ldsm_x4(b, bs_u +
                    (uint32_t)((((buf * 2 + 0) * BN + wn0 + b_roff) * BKP
                                + kk * 16 + b_coff) * 2));
#pragma unroll
                for (int i = 0; i < MT; i++) mma16816(acc_h[i][0], a[i], b[0], b[1]);
#pragma unroll
                for (int i = 0; i < MT; i++) mma16816(acc_h[i][1], a[i], b[2], b[3]);
            }
            {
                uint32_t b[4];
                ldsm_x4(b, bs_u +
                    (uint32_t)((((buf * 2 + 1) * BN + wn0 + b_roff) * BKP
                                + kk * 16 + b_coff) * 2));
#pragma unroll
                for (int i = 0; i < MT; i++) mma16816(acc_l[i][0], a[i], b[0], b[1]);
#pragma unroll
                for (int i = 0; i < MT; i++) mma16816(acc_l[i][1], a[i], b[2], b[3]);
            }
        }
        __syncthreads();
    }

    const int grp = lane >> 2, q = lane & 3;
#pragma unroll
    for (int i = 0; i < MT; i++) {
#pragma unroll
        for (int j = 0; j < NT; j++) {
            int row0 = bm0 + wm0 + i * 16 + grp;
            int row1 = row0 + 8;
            int col  = wn0 + j * 8 + q * 2;
            float bv0 = bias[col];
            float bv1 = bias[col + 1];
            float v00 = fmaf(acc_l[i][j][0], LO_INV_SCALE, acc_h[i][j][0]) + bv0;
            float v01 = fmaf(acc_l[i][j][1], LO_INV_SCALE, acc_h[i][j][1]) + bv1;
            float v10 = fmaf(acc_l[i][j][2], LO_INV_SCALE, acc_h[i][j][2]) + bv0;
            float v11 = fmaf(acc_l[i][j][3], LO_INV_SCALE, acc_h[i][j][3]) + bv1;
            *(float2*)&C[(size_t)row0 * N + col] = make_float2(v00, v01);
            *(float2*)&C[(size_t)row1 * N + col] = make_float2(v10, v11);
        }
    }
}

// ======================= LIF layer 1: currents -> bit-packed spikes =======================
// mem_t = 0.9*mem + cur_t - spk_{t-1};  spk_t = (mem_t - 1 > 0). _rn ops forbid FMA fusion.
__global__ void lif1_kernel(const float* __restrict__ cur, uint32_t* __restrict__ spkb) {
    int idx = blockIdx.x * blockDim.x + threadIdx.x;   // = b*HID + h
    int b = idx >> 12;                                  // HID_DIM = 4096
    int h = idx & (HID_DIM - 1);
    int lane = threadIdx.x & 31;
    float mem = 0.f, sp = 0.f;
#pragma unroll
    for (int t = 0; t < T_STEPS; t++) {
        float c = cur[(size_t)t * BATCH * HID_DIM + idx];
        mem = __fsub_rn(__fadd_rn(__fmul_rn(0.9f, mem), c), sp);
        sp  = (mem > 1.0f) ? 1.f : 0.f;
        uint32_t bits = __ballot_sync(0xFFFFFFFFu, mem > 1.0f);
        if (lane == 0)
            spkb[(size_t)(t * BATCH + b) * HIDW + (h >> 5)] = bits;
    }
}

// ======================= LIF layer 2: currents -> spike counts =======================
__global__ void lif2_kernel(const float* __restrict__ cur, float* __restrict__ out) {
    int idx = blockIdx.x * blockDim.x + threadIdx.x;   // = b*OUT + o
    if (idx >= BATCH * OUT_DIM) return;
    float mem = 0.f, sp = 0.f, cnt = 0.f;
#pragma unroll
    for (int t = 0; t < T_STEPS; t++) {
        float c = cur[(size_t)t * BATCH * OUT_DIM + idx];
        mem = __fsub_rn(__fadd_rn(__fmul_rn(0.9f, mem), c), sp);
        sp  = (mem > 1.0f) ? 1.f : 0.f;
        cnt += sp;
    }
    out[idx] = cnt;
}

// ======================= launch =======================
extern "C" void kernel_launch(void* const* d_in, const int* in_sizes, int n_in,
                              void* d_out, int out_size) {
    const float* x  = (const float*)d_in[0];   // [25,1024,1024]
    const float* w1 = (const float*)d_in[1];   // [4096,1024]
    const float* b1 = (const float*)d_in[2];   // [4096]
    const float* w2 = (const float*)d_in[3];   // [64,4096]
    const float* b2 = (const float*)d_in[4];   // [64]
    float* out = (float*)d_out;                // [1024,64]

    __half *A, *w1hi, *w1lo, *w2hi, *w2lo;
    uint32_t* spkb;
    float *cur1, *cur2;
    cudaGetSymbolAddress((void**)&A,    g_A);
    cudaGetSymbolAddress((void**)&w1hi, g_w1hi);
    cudaGetSymbolAddress((void**)&w1lo, g_w1lo);
    cudaGetSymbolAddress((void**)&w2hi, g_w2hi);
    cudaGetSymbolAddress((void**)&w2lo, g_w2lo);
    cudaGetSymbolAddress((void**)&spkb, g_spkb);
    cudaGetSymbolAddress((void**)&cur1, g_cur1);
    cudaGetSymbolAddress((void**)&cur2, g_cur2);

    // GEMM1 (frozen optimum): BM=128,BN=64,WM=32,WN=32 -> 8 warps, 2 CTAs/SM.
    constexpr int SMEM1 = 2 * (128 * 72 + 2 * 64 * 72) * 2;   // 73728 B
    // GEMM2 bits: 55296 B/CTA; 3 CTAs/SM = 165888 B <= 227 KB.
    constexpr int SMEM2 = 2 * (64 * 72 + 2 * 64 * 72) * 2;
    cudaFuncSetAttribute((const void*)gemm_hilo<128, 64, 64, 32, 32, 2>,
                         cudaFuncAttributeMaxDynamicSharedMemorySize, SMEM1);
    cudaFuncSetAttribute((const void*)gemm2_bits,
                         cudaFuncAttributeMaxDynamicSharedMemorySize, SMEM2);

    // 1) merged prep (single launch)
    k_prep<<<4096, 256>>>(x, A, w1, w1hi, w1lo, w2, w2hi, w2lo);

    // 2) GEMM1: cur1[25600,4096] = A[25600,1024] @ w1^T + b1  (grid 64x200)
    gemm_hilo<128, 64, 64, 32, 32, 2>
        <<<dim3(HID_DIM / 64, M_ROWS / 128), 256, SMEM1>>>(
            A, w1hi, w1lo, b1, cur1, M_ROWS, HID_DIM, IN_DIM);

    // 3) LIF layer 1 -> bit-packed spikes
    lif1_kernel<<<(BATCH * HID_DIM) / 256, 256>>>(cur1, spkb);

    // 4) GEMM2: cur2[25600,64] = spikes @ w2^T + b2  (grid 1x400, one wave @3/SM)
    gemm2_bits<<<dim3(1, M_ROWS / G2_BM), 256, SMEM2>>>(
        spkb, w2hi, w2lo, b2, cur2, M_ROWS, OUT_DIM, HID_DIM);

    // 5) LIF layer 2 + spike counting
    lif2_kernel<<<(BATCH * OUT_DIM) / 256, 256>>>(cur2, out);
}

// round 14
// speedup vs baseline: 1.2977x; 1.0015x over previous
#include <cuda_runtime.h>
#include <cuda_fp16.h>
#include <cstdint>
#include <cstddef>

// ======================= problem dims (fixed) =======================
#define T_STEPS 25
#define BATCH   1024
#define IN_DIM  1024
#define HID_DIM 4096
#define OUT_DIM 64
#define M_ROWS  (T_STEPS * BATCH)   // 25600
#define HIDW    (HID_DIM / 32)      // 128 bit-words per row

#define LO_SCALE     1024.0f
#define LO_INV_SCALE 0.0009765625f  // exact 2^-10

// ======================= static device scratch =======================
__device__ __half   g_A    [(size_t)M_ROWS * IN_DIM];     // fp16 input spikes (exact 0/1)
__device__ __half   g_w1hi [(size_t)HID_DIM * IN_DIM];
__device__ __half   g_w1lo [(size_t)HID_DIM * IN_DIM];    // (w - hi) * 1024, fp16-normal
__device__ __half   g_w2hi [(size_t)OUT_DIM * HID_DIM];
__device__ __half   g_w2lo [(size_t)OUT_DIM * HID_DIM];
__device__ float    g_cur1 [(size_t)M_ROWS * HID_DIM];    // layer-1 currents
__device__ uint32_t g_spkb [(size_t)M_ROWS * HIDW];       // layer-1 spikes, bit-packed
__device__ float    g_cur2 [(size_t)M_ROWS * OUT_DIM];    // layer-2 currents

// ======================= helpers =======================
__device__ __forceinline__ void cp16(void* dst_smem, const void* src_gmem) {
    uint32_t d = (uint32_t)__cvta_generic_to_shared(dst_smem);
    asm volatile("cp.async.cg.shared.global [%0], [%1], 16;" :: "r"(d), "l"(src_gmem));
}
__device__ __forceinline__ void cp_commit() { asm volatile("cp.async.commit_group;"); }
__device__ __forceinline__ void cp_wait1()  { asm volatile("cp.async.wait_group 1;"); }
__device__ __forceinline__ void cp_wait0()  { asm volatile("cp.async.wait_group 0;"); }

__device__ __forceinline__ void ldsm_x4(uint32_t* r, uint32_t saddr) {
    asm volatile("ldmatrix.sync.aligned.m8n8.x4.shared.b16 {%0,%1,%2,%3}, [%4];"
        : "=r"(r[0]), "=r"(r[1]), "=r"(r[2]), "=r"(r[3]) : "r"(saddr));
}

__device__ __forceinline__ void mma16816(float* c, const uint32_t* a, uint32_t b0, uint32_t b1) {
    asm volatile(
        "mma.sync.aligned.m16n8k16.row.col.f32.f16.f16.f32 "
        "{%0,%1,%2,%3}, {%4,%5,%6,%7}, {%8,%9}, {%0,%1,%2,%3};"
        : "+f"(c[0]), "+f"(c[1]), "+f"(c[2]), "+f"(c[3])
        : "r"(a[0]), "r"(a[1]), "r"(a[2]), "r"(a[3]), "r"(b0), "r"(b1));
}

// ======================= merged prep kernel =======================
#define N_CVT (M_ROWS * IN_DIM)       // 26214400
#define N_W1  (HID_DIM * IN_DIM)      // 4194304
#define N_W2  (OUT_DIM * HID_DIM)     // 262144
__global__ void k_prep(const float* __restrict__ x, __half* __restrict__ A,
                       const float* __restrict__ w1, __half* __restrict__ w1hi,
                       __half* __restrict__ w1lo,
                       const float* __restrict__ w2, __half* __restrict__ w2hi,
                       __half* __restrict__ w2lo) {
    const int total = N_CVT + N_W1 + N_W2;
    for (int i = blockIdx.x * blockDim.x + threadIdx.x; i < total;
         i += gridDim.x * blockDim.x) {
        if (i < N_CVT) {
            A[i] = __float2half_rn(x[i]);
        } else {
            const float* w; __half *hi, *lo; int j;
            if (i < N_CVT + N_W1) { j = i - N_CVT; w = w1; hi = w1hi; lo = w1lo; }
            else                  { j = i - N_CVT - N_W1; w = w2; hi = w2hi; lo = w2lo; }
            float v = w[j];
            __half h = __float2half_rn(v);
            hi[j] = h;
            lo[j] = __float2half_rn(__fmul_rn(__fsub_rn(v, __half2float(h)), LO_SCALE));
        }
    }
}

// ====== GEMM1: C[M,N] = A[M,K] @ (Whi + Wlo/1024)[N,K]^T + bias (two-plane accum) ======
// FROZEN optimum (round 5). 2-stage cp.async; ldmatrix.x4; separate fp32 accumulators
// per plane, combined as acc_hi + acc_lo/1024 + bias in the epilogue.
template <int BM, int BN, int BK, int WM, int WN, int MINCTA>
__global__ void __launch_bounds__((BM / WM) * (BN / WN) * 32, MINCTA)
gemm_hilo(const __half* __restrict__ A,
          const __half* __restrict__ Whi,
          const __half* __restrict__ Wlo,
          const float* __restrict__ bias,
          float* __restrict__ C,
          int M, int N, int K)
{
    constexpr int BKP  = BK + 8;
    constexpr int NW   = (BM / WM) * (BN / WN);
    constexpr int NTH  = NW * 32;
    constexpr int MT   = WM / 16;
    constexpr int NT   = WN / 8;
    constexpr int KCH  = BK / 8;
    constexpr int ACH  = BM * KCH;
    constexpr int BCH  = BN * KCH;

    extern __shared__ __align__(16) unsigned char smem_raw[];
    __half* As = reinterpret_cast<__half*>(smem_raw);   // [2][BM][BKP]
    __half* Bs = As + 2 * BM * BKP;                      // [2][2][BN][BKP]

    const int tid  = threadIdx.x;
    const int wid  = tid >> 5;
    const int lane = tid & 31;

    const int wm0 = (wid % (BM / WM)) * WM;
    const int wn0 = (wid / (BM / WM)) * WN;
    const int bm0 = blockIdx.y * BM;
    const int bn0 = blockIdx.x * BN;
    const int NK  = K / BK;

    const int mi = lane >> 3, rr = lane & 7;
    const int a_roff = (mi & 1) * 8 + rr;
    const int a_coff = (mi >> 1) * 8;
    const int b_roff = (mi >> 1) * 8 + rr;
    const int b_coff = (mi & 1) * 8;

    const uint32_t as_u = (uint32_t)__cvta_generic_to_shared(As);
    const uint32_t bs_u = (uint32_t)__cvta_generic_to_shared(Bs);

    float acc_h[MT][NT][4];
    float acc_l[MT][NT][4];
#pragma unroll
    for (int i = 0; i < MT; i++)
#pragma unroll
        for (int j = 0; j < NT; j++)
#pragma unroll
            for (int e = 0; e < 4; e++) { acc_h[i][j][e] = 0.f; acc_l[i][j][e] = 0.f; }

    auto load_stage = [&](int stage, int kt) {
        const int k0 = kt * BK;
#pragma unroll
        for (int c = tid; c < ACH; c += NTH) {
            int row = c / KCH, kc = (c % KCH) * 8;
            cp16(&As[(stage * BM + row) * BKP + kc],
                 A + (size_t)(bm0 + row) * K + k0 + kc);
        }
#pragma unroll
        for (int c = tid; c < BCH; c += NTH) {
            int row = c / KCH, kc = (c % KCH) * 8;
            size_t g = (size_t)(bn0 + row) * K + k0 + kc;
            cp16(&Bs[((stage * 2 + 0) * BN + row) * BKP + kc], Whi + g);
            cp16(&Bs[((stage * 2 + 1) * BN + row) * BKP + kc], Wlo + g);
        }
    };

    load_stage(0, 0);
    cp_commit();

    for (int kt = 0; kt < NK; kt++) {
        const int buf = kt & 1;
        if (kt + 1 < NK) {
            load_stage(buf ^ 1, kt + 1);
            cp_commit();
            cp_wait1();
        } else {
            cp_wait0();
        }
        __syncthreads();

#pragma unroll
        for (int kk = 0; kk < BK / 16; kk++) {
            uint32_t a[MT][4];
#pragma unroll
            for (int i = 0; i < MT; i++)
                ldsm_x4(a[i], as_u +
                    (uint32_t)(((buf * BM + wm0 + i * 16 + a_roff) * BKP
                                + kk * 16 + a_coff) * 2));
#pragma unroll
            for (int jp = 0; jp < NT / 2; jp++) {
                uint32_t b[4];
                ldsm_x4(b, bs_u +
                    (uint32_t)((((buf * 2 + 0) * BN + wn0 + jp * 16 + b_roff) * BKP
                                + kk * 16 + b_coff) * 2));
#pragma unroll
                for (int i = 0; i < MT; i++) mma16816(acc_h[i][2 * jp],     a[i], b[0], b[1]);
#pragma unroll
                for (int i = 0; i < MT; i++) mma16816(acc_h[i][2 * jp + 1], a[i], b[2], b[3]);
            }
#pragma unroll
            for (int jp = 0; jp < NT / 2; jp++) {
                uint32_t b[4];
                ldsm_x4(b, bs_u +
                    (uint32_t)((((buf * 2 + 1) * BN + wn0 + jp * 16 + b_roff) * BKP
                                + kk * 16 + b_coff) * 2));
#pragma unroll
                for (int i = 0; i < MT; i++) mma16816(acc_l[i][2 * jp],     a[i], b[0], b[1]);
#pragma unroll
                for (int i = 0; i < MT; i++) mma16816(acc_l[i][2 * jp + 1], a[i], b[2], b[3]);
            }
        }
        __syncthreads();
    }

    const int grp = lane >> 2, q = lane & 3;
#pragma unroll
    for (int i = 0; i < MT; i++) {
#pragma unroll
        for (int j = 0; j < NT; j++) {
            int row0 = bm0 + wm0 + i * 16 + grp;
            int row1 = row0 + 8;
            int col  = bn0 + wn0 + j * 8 + q * 2;
            float bv0 = bias[col];
            float bv1 = bias[col + 1];
            float v00 = fmaf(acc_l[i][j][0], LO_INV_SCALE, acc_h[i][j][0]) + bv0;
            float v01 = fmaf(acc_l[i][j][1], LO_INV_SCALE, acc_h[i][j][1]) + bv1;
            float v10 = fmaf(acc_l[i][j][2], LO_INV_SCALE, acc_h[i][j][2]) + bv0;
            float v11 = fmaf(acc_l[i][j][3], LO_INV_SCALE, acc_h[i][j][3]) + bv1;
            *(float2*)&C[(size_t)row0 * N + col] = make_float2(v00, v01);
            *(float2*)&C[(size_t)row1 * N + col] = make_float2(v10, v11);
        }
    }
}

// ====== GEMM2 (bit-packed A): C[M,64] = spikes[M,K] @ (Whi + Wlo/1024)^T + bias ======
// BM=64, BN=64, BK=64; 4 warps (128 thr), WM=32, WN=32 -> MMA:LDSM = 2.67 (the
// measured-optimal knee). 4 CTAs/SM (16 warps) -> grid 400 in one wave (592 slots).
#define G2_BM 64
#define G2_BK 64
#define G2_BKP 72
__global__ void __launch_bounds__(128, 4)
gemm2_bits(const uint32_t* __restrict__ Abits,
           const __half* __restrict__ Whi,
           const __half* __restrict__ Wlo,
           const float* __restrict__ bias,
           float* __restrict__ C,
           int M, int N, int K)
{
    constexpr int BM = G2_BM, BN = 64, BK = G2_BK, BKP = G2_BKP;
    constexpr int MT = 2, NT = 4;               // WM=32, WN=32
    constexpr int KCH = BK / 8;                 // 8
    constexpr int BCH = BN * KCH;               // 512

    extern __shared__ __align__(16) unsigned char smem_raw[];
    __half* As = reinterpret_cast<__half*>(smem_raw);   // [2][BM][BKP]
    __half* Bs = As + 2 * BM * BKP;                      // [2][2][BN][BKP]

    const int tid  = threadIdx.x;
    const int wid  = tid >> 5;                  // 0..3
    const int lane = tid & 31;

    const int wm0 = (wid & 1) * 32;             // 2 warps along M
    const int wn0 = (wid >> 1) * 32;            // 2 warps along N
    const int bm0 = blockIdx.y * BM;
    const int NK  = K / BK;
    const int KW  = K >> 5;                     // bit-words per row

    const int mi = lane >> 3, rr = lane & 7;
    const int a_roff = (mi & 1) * 8 + rr;
    const int a_coff = (mi >> 1) * 8;
    const int b_roff = (mi >> 1) * 8 + rr;
    const int b_coff = (mi & 1) * 8;

    const uint32_t as_u = (uint32_t)__cvta_generic_to_shared(As);
    const uint32_t bs_u = (uint32_t)__cvta_generic_to_shared(Bs);

    float acc_h[MT][NT][4];
    float acc_l[MT][NT][4];
#pragma unroll
    for (int i = 0; i < MT; i++)
#pragma unroll
        for (int j = 0; j < NT; j++)
#pragma unroll
            for (int e = 0; e < 4; e++) { acc_h[i][j][e] = 0.f; acc_l[i][j][e] = 0.f; }

    auto load_stage = [&](int stage, int kt) {
        const int k0 = kt * BK;
        // A: 64 rows x 64 bits = 128 word-tasks, one per thread; expand to fp16 {0,1}
        {
            int row = tid >> 1, half = tid & 1;
            uint32_t w = Abits[(size_t)(bm0 + row) * KW + (kt << 1) + half];
            __half* dst = &As[(stage * BM + row) * BKP + half * 32];
#pragma unroll
            for (int g = 0; g < 8; g++) {
                uint32_t b4 = w >> (4 * g);
                uint32_t lo = ((b4 & 1) * 0x3C00u) | (((b4 >> 1) & 1) * 0x3C000000u);
                uint32_t hi = (((b4 >> 2) & 1) * 0x3C00u) | (((b4 >> 3) & 1) * 0x3C000000u);
                *(uint2*)(dst + g * 4) = make_uint2(lo, hi);
            }
        }
        // B hi/lo planes via cp.async (512 chunks per plane, 128 threads)
#pragma unroll
        for (int c = tid; c < BCH; c += 128) {
            int row = c / KCH, kc = (c % KCH) * 8;
            size_t g = (size_t)row * K + k0 + kc;
            cp16(&Bs[((stage * 2 + 0) * BN + row) * BKP + kc], Whi + g);
            cp16(&Bs[((stage * 2 + 1) * BN + row) * BKP + kc], Wlo + g);
        }
    };

    load_stage(0, 0);
    cp_commit();

    for (int kt = 0; kt < NK; kt++) {
        const int buf = kt & 1;
        if (kt + 1 < NK) {
            load_stage(buf ^ 1, kt + 1);
            cp_commit();
            cp_wait1();
        } else {
            cp_wait0();
        }
        __syncthreads();

#pragma unroll
        for (int kk = 0; kk < BK / 16; kk++) {
            uint32_t a[MT][4];
#pragma unroll
            for (int i = 0; i < MT; i++)
                ldsm_x4(a[i], as_u +
                    (uint32_t)(((buf * BM + wm0 + i * 16 + a_roff) * BKP
                                + kk * 16 + a_coff) * 2));
#pragma unroll
            for (int jp = 0; jp < NT / 2; jp++) {
                uint32_t b[4];
                ldsm_x4(b, bs_u +
                    (uint32_t)((((buf * 2 + 0) * BN + wn0 + jp * 16 + b_roff) * BKP
                                + kk * 16 + b_coff) * 2));
#pragma unroll
                for (int i = 0; i < MT; i++) mma16816(acc_h[i][2 * jp],     a[i], b[0], b[1]);
#pragma unroll
                for (int i = 0; i < MT; i++) mma16816(acc_h[i][2 * jp + 1], a[i], b[2], b[3]);
            }
#pragma unroll
            for (int jp = 0; jp < NT / 2; jp++) {
                uint32_t b[4];
                ldsm_x4(b, bs_u +
                    (uint32_t)((((buf * 2 + 1) * BN + wn0 + jp * 16 + b_roff) * BKP
                                + kk * 16 + b_coff) * 2));
#pragma unroll
                for (int i = 0; i < MT; i++) mma16816(acc_l[i][2 * jp],     a[i], b[0], b[1]);
#pragma unroll
                for (int i = 0; i < MT; i++) mma16816(acc_l[i][2 * jp + 1], a[i], b[2], b[3]);
            }
        }
        __syncthreads();
    }

    const int grp = lane >> 2, q = lane & 3;
#pragma unroll
    for (int i = 0; i < MT; i++) {
#pragma unroll
        for (int j = 0; j < NT; j++) {
            int row0 = bm0 + wm0 + i * 16 + grp;
            int row1 = row0 + 8;
            int col  = wn0 + j * 8 + q * 2;
            float bv0 = bias[col];
            float bv1 = bias[col + 1];
            float v00 = fmaf(acc_l[i][j][0], LO_INV_SCALE, acc_h[i][j][0]) + bv0;
            float v01 = fmaf(acc_l[i][j][1], LO_INV_SCALE, acc_h[i][j][1]) + bv1;
            float v10 = fmaf(acc_l[i][j][2], LO_INV_SCALE, acc_h[i][j][2]) + bv0;
            float v11 = fmaf(acc_l[i][j][3], LO_INV_SCALE, acc_h[i][j][3]) + bv1;
            *(float2*)&C[(size_t)row0 * N + col] = make_float2(v00, v01);
            *(float2*)&C[(size_t)row1 * N + col] = make_float2(v10, v11);
        }
    }
}

// ======================= LIF layer 1: currents -> bit-packed spikes =======================
__global__ void lif1_kernel(const float* __restrict__ cur, uint32_t* __restrict__ spkb) {
    int idx = blockIdx.x * blockDim.x + threadIdx.x;   // = b*HID + h
    int b = idx >> 12;                                  // HID_DIM = 4096
    int h = idx & (HID_DIM - 1);
    int lane = threadIdx.x & 31;
    float mem = 0.f, sp = 0.f;
#pragma unroll
    for (int t = 0; t < T_STEPS; t++) {
        float c = cur[(size_t)t * BATCH * HID_DIM + idx];
        mem = __fsub_rn(__fadd_rn(__fmul_rn(0.9f, mem), c), sp);
        sp  = (mem > 1.0f) ? 1.f : 0.f;
        uint32_t bits = __ballot_sync(0xFFFFFFFFu, mem > 1.0f);
        if (lane == 0)
            spkb[(size_t)(t * BATCH + b) * HIDW + (h >> 5)] = bits;
    }
}

// ======================= LIF layer 2: currents -> spike counts =======================
__global__ void lif2_kernel(const float* __restrict__ cur, float* __restrict__ out) {
    int idx = blockIdx.x * blockDim.x + threadIdx.x;   // = b*OUT + o
    if (idx >= BATCH * OUT_DIM) return;
    float mem = 0.f, sp = 0.f, cnt = 0.f;
#pragma unroll
    for (int t = 0; t < T_STEPS; t++) {
        float c = cur[(size_t)t * BATCH * OUT_DIM + idx];
        mem = __fsub_rn(__fadd_rn(__fmul_rn(0.9f, mem), c), sp);
        sp  = (mem > 1.0f) ? 1.f : 0.f;
        cnt += sp;
    }
    out[idx] = cnt;
}

// ======================= launch =======================
extern "C" void kernel_launch(void* const* d_in, const int* in_sizes, int n_in,
                              void* d_out, int out_size) {
    const float* x  = (const float*)d_in[0];   // [25,1024,1024]
    const float* w1 = (const float*)d_in[1];   // [4096,1024]
    const float* b1 = (const float*)d_in[2];   // [4096]
    const float* w2 = (const float*)d_in[3];   // [64,4096]
    const float* b2 = (const float*)d_in[4];   // [64]
    float* out = (float*)d_out;                // [1024,64]

    __half *A, *w1hi, *w1lo, *w2hi, *w2lo;
    uint32_t* spkb;
    float *cur1, *cur2;
    cudaGetSymbolAddress((void**)&A,    g_A);
    cudaGetSymbolAddress((void**)&w1hi, g_w1hi);
    cudaGetSymbolAddress((void**)&w1lo, g_w1lo);
    cudaGetSymbolAddress((void**)&w2hi, g_w2hi);
    cudaGetSymbolAddress((void**)&w2lo, g_w2lo);
    cudaGetSymbolAddress((void**)&spkb, g_spkb);
    cudaGetSymbolAddress((void**)&cur1, g_cur1);
    cudaGetSymbolAddress((void**)&cur2, g_cur2);

    // GEMM1 (frozen optimum): BM=128,BN=64,WM=32,WN=32 -> 8 warps, 2 CTAs/SM.
    constexpr int SMEM1 = 2 * (128 * 72 + 2 * 64 * 72) * 2;   // 73728 B
    // GEMM2 bits: 55296 B/CTA; 4 CTAs/SM = 221184 B <= 228 KB.
    constexpr int SMEM2 = 2 * (64 * 72 + 2 * 64 * 72) * 2;
    cudaFuncSetAttribute((const void*)gemm_hilo<128, 64, 64, 32, 32, 2>,
                         cudaFuncAttributeMaxDynamicSharedMemorySize, SMEM1);
    cudaFuncSetAttribute((const void*)gemm2_bits,
                         cudaFuncAttributeMaxDynamicSharedMemorySize, SMEM2);

    // 1) merged prep (single launch)
    k_prep<<<4096, 256>>>(x, A, w1, w1hi, w1lo, w2, w2hi, w2lo);

    // 2) GEMM1: cur1[25600,4096] = A[25600,1024] @ w1^T + b1  (grid 64x200)
    gemm_hilo<128, 64, 64, 32, 32, 2>
        <<<dim3(HID_DIM / 64, M_ROWS / 128), 256, SMEM1>>>(
            A, w1hi, w1lo, b1, cur1, M_ROWS, HID_DIM, IN_DIM);

    // 3) LIF layer 1 -> bit-packed spikes
    lif1_kernel<<<(BATCH * HID_DIM) / 256, 256>>>(cur1, spkb);

    // 4) GEMM2: cur2[25600,64] = spikes @ w2^T + b2  (grid 1x400, one wave @4/SM)
    gemm2_bits<<<dim3(1, M_ROWS / G2_BM), 128, SMEM2>>>(
        spkb, w2hi, w2lo, b2, cur2, M_ROWS, OUT_DIM, HID_DIM);

    // 5) LIF layer 2 + spike counting
    lif2_kernel<<<(BATCH * OUT_DIM) / 256, 256>>>(cur2, out);
}

// round 15
// speedup vs baseline: 1.3342x; 1.0281x over previous
#include <cuda_runtime.h>
#include <cuda_fp16.h>
#include <cstdint>
#include <cstddef>

// ======================= problem dims (fixed) =======================
#define T_STEPS 25
#define BATCH   1024
#define IN_DIM  1024
#define HID_DIM 4096
#define OUT_DIM 64
#define M_ROWS  (T_STEPS * BATCH)   // 25600
#define HIDW    (HID_DIM / 32)      // 128 bit-words per row

#define LO_SCALE     1024.0f
#define LO_INV_SCALE 0.0009765625f  // exact 2^-10

// ======================= static device scratch =======================
__device__ __half   g_A    [(size_t)M_ROWS * IN_DIM];     // fp16 input spikes (exact 0/1)
__device__ __half   g_w1hi [(size_t)HID_DIM * IN_DIM];
__device__ __half   g_w1lo [(size_t)HID_DIM * IN_DIM];    // (w - hi) * 1024, fp16-normal
__device__ __half   g_w2hi [(size_t)OUT_DIM * HID_DIM];
__device__ __half   g_w2lo [(size_t)OUT_DIM * HID_DIM];
__device__ float    g_cur1 [(size_t)M_ROWS * HID_DIM];    // layer-1 currents
__device__ uint32_t g_spkb [(size_t)M_ROWS * HIDW];       // layer-1 spikes, bit-packed
__device__ float    g_cur2 [(size_t)M_ROWS * OUT_DIM];    // layer-2 currents

// ======================= helpers =======================
__device__ __forceinline__ void cp16(void* dst_smem, const void* src_gmem) {
    uint32_t d = (uint32_t)__cvta_generic_to_shared(dst_smem);
    asm volatile("cp.async.cg.shared.global [%0], [%1], 16;" :: "r"(d), "l"(src_gmem));
}
__device__ __forceinline__ void cp_commit() { asm volatile("cp.async.commit_group;"); }
__device__ __forceinline__ void cp_wait1()  { asm volatile("cp.async.wait_group 1;"); }
__device__ __forceinline__ void cp_wait0()  { asm volatile("cp.async.wait_group 0;"); }

__device__ __forceinline__ void ldsm_x4(uint32_t* r, uint32_t saddr) {
    asm volatile("ldmatrix.sync.aligned.m8n8.x4.shared.b16 {%0,%1,%2,%3}, [%4];"
        : "=r"(r[0]), "=r"(r[1]), "=r"(r[2]), "=r"(r[3]) : "r"(saddr));
}

__device__ __forceinline__ void mma16816(float* c, const uint32_t* a, uint32_t b0, uint32_t b1) {
    asm volatile(
        "mma.sync.aligned.m16n8k16.row.col.f32.f16.f16.f32 "
        "{%0,%1,%2,%3}, {%4,%5,%6,%7}, {%8,%9}, {%0,%1,%2,%3};"
        : "+f"(c[0]), "+f"(c[1]), "+f"(c[2]), "+f"(c[3])
        : "r"(a[0]), "r"(a[1]), "r"(a[2]), "r"(a[3]), "r"(b0), "r"(b1));
}

__device__ __forceinline__ uint32_t h2bits(__half2 h) {
    return *reinterpret_cast<uint32_t*>(&h);
}

// ======================= merged prep kernel (vectorized, bit-identical) ===============
// Segment 1: cvt input spikes fp32 -> fp16.  Segments 2/3: split w1/w2 -> hi/lo planes.
// __floats2half2_rn applies the same round-to-nearest as scalar __float2half_rn.
#define N_CVT (M_ROWS * IN_DIM)       // 26214400
#define N_W1  (HID_DIM * IN_DIM)      // 4194304
#define N_W2  (OUT_DIM * HID_DIM)     // 262144
__global__ void k_prep(const float4* __restrict__ x, uint2* __restrict__ A,
                       const float4* __restrict__ w1, uint2* __restrict__ w1hi,
                       uint2* __restrict__ w1lo,
                       const float4* __restrict__ w2, uint2* __restrict__ w2hi,
                       uint2* __restrict__ w2lo) {
    const int nc = N_CVT / 4, n1 = N_W1 / 4, n2 = N_W2 / 4;
    const int total = nc + n1 + n2;
    for (int i = blockIdx.x * blockDim.x + threadIdx.x; i < total;
         i += gridDim.x * blockDim.x) {
        if (i < nc) {
            float4 v = x[i];
            A[i] = make_uint2(h2bits(__floats2half2_rn(v.x, v.y)),
                              h2bits(__floats2half2_rn(v.z, v.w)));
        } else {
            const float4* w; uint2 *hi, *lo; int j;
            if (i < nc + n1) { j = i - nc; w = w1; hi = w1hi; lo = w1lo; }
            else             { j = i - nc - n1; w = w2; hi = w2hi; lo = w2lo; }
            float4 v = w[j];
            __half h0 = __float2half_rn(v.x), h1 = __float2half_rn(v.y);
            __half h2 = __float2half_rn(v.z), h3 = __float2half_rn(v.w);
            hi[j] = make_uint2(h2bits(__halves2half2(h0, h1)),
                               h2bits(__halves2half2(h2, h3)));
            // residual scaled into fp16-normal range; own accumulator downstream
            lo[j] = make_uint2(
                h2bits(__floats2half2_rn(
                    __fmul_rn(__fsub_rn(v.x, __half2float(h0)), LO_SCALE),
                    __fmul_rn(__fsub_rn(v.y, __half2float(h1)), LO_SCALE))),
                h2bits(__floats2half2_rn(
                    __fmul_rn(__fsub_rn(v.z, __half2float(h2)), LO_SCALE),
                    __fmul_rn(__fsub_rn(v.w, __half2float(h3)), LO_SCALE))));
        }
    }
}

// ====== GEMM1: C[M,N] = A[M,K] @ (Whi + Wlo/1024)[N,K]^T + bias (two-plane accum) ======
// FROZEN optimum (round 5). 2-stage cp.async; ldmatrix.x4; separate fp32 accumulators
// per plane, combined as acc_hi + acc_lo/1024 + bias in the epilogue.
template <int BM, int BN, int BK, int WM, int WN, int MINCTA>
__global__ void __launch_bounds__((BM / WM) * (BN / WN) * 32, MINCTA)
gemm_hilo(const __half* __restrict__ A,
          const __half* __restrict__ Whi,
          const __half* __restrict__ Wlo,
          const float* __restrict__ bias,
          float* __restrict__ C,
          int M, int N, int K)
{
    constexpr int BKP  = BK + 8;
    constexpr int NW   = (BM / WM) * (BN / WN);
    constexpr int NTH  = NW * 32;
    constexpr int MT   = WM / 16;
    constexpr int NT   = WN / 8;
    constexpr int KCH  = BK / 8;
    constexpr int ACH  = BM * KCH;
    constexpr int BCH  = BN * KCH;

    extern __shared__ __align__(16) unsigned char smem_raw[];
    __half* As = reinterpret_cast<__half*>(smem_raw);   // [2][BM][BKP]
    __half* Bs = As + 2 * BM * BKP;                      // [2][2][BN][BKP]

    const int tid  = threadIdx.x;
    const int wid  = tid >> 5;
    const int lane = tid & 31;

    const int wm0 = (wid % (BM / WM)) * WM;
    const int wn0 = (wid / (BM / WM)) * WN;
    const int bm0 = blockIdx.y * BM;
    const int bn0 = blockIdx.x * BN;
    const int NK  = K / BK;

    const int mi = lane >> 3, rr = lane & 7;
    const int a_roff = (mi & 1) * 8 + rr;
    const int a_coff = (mi >> 1) * 8;
    const int b_roff = (mi >> 1) * 8 + rr;
    const int b_coff = (mi & 1) * 8;

    const uint32_t as_u = (uint32_t)__cvta_generic_to_shared(As);
    const uint32_t bs_u = (uint32_t)__cvta_generic_to_shared(Bs);

    float acc_h[MT][NT][4];
    float acc_l[MT][NT][4];
#pragma unroll
    for (int i = 0; i < MT; i++)
#pragma unroll
        for (int j = 0; j < NT; j++)
#pragma unroll
            for (int e = 0; e < 4; e++) { acc_h[i][j][e] = 0.f; acc_l[i][j][e] = 0.f; }

    auto load_stage = [&](int stage, int kt) {
        const int k0 = kt * BK;
#pragma unroll
        for (int c = tid; c < ACH; c += NTH) {
            int row = c / KCH, kc = (c % KCH) * 8;
            cp16(&As[(stage * BM + row) * BKP + kc],
                 A + (size_t)(bm0 + row) * K + k0 + kc);
        }
#pragma unroll
        for (int c = tid; c < BCH; c += NTH) {
            int row = c / KCH, kc = (c % KCH) * 8;
            size_t g = (size_t)(bn0 + row) * K + k0 + kc;
            cp16(&Bs[((stage * 2 + 0) * BN + row) * BKP + kc], Whi + g);
            cp16(&Bs[((stage * 2 + 1) * BN + row) * BKP + kc], Wlo + g);
        }
    };

    load_stage(0, 0);
    cp_commit();

    for (int kt = 0; kt < NK; kt++) {
        const int buf = kt & 1;
        if (kt + 1 < NK) {
            load_stage(buf ^ 1, kt + 1);
            cp_commit();
            cp_wait1();
        } else {
            cp_wait0();
        }
        __syncthreads();

#pragma unroll
        for (int kk = 0; kk < BK / 16; kk++) {
            uint32_t a[MT][4];
#pragma unroll
            for (int i = 0; i < MT; i++)
                ldsm_x4(a[i], as_u +
                    (uint32_t)(((buf * BM + wm0 + i * 16 + a_roff) * BKP
                                + kk * 16 + a_coff) * 2));
#pragma unroll
            for (int jp = 0; jp < NT / 2; jp++) {
                uint32_t b[4];
                ldsm_x4(b, bs_u +
                    (uint32_t)((((buf * 2 + 0) * BN + wn0 + jp * 16 + b_roff) * BKP
                                + kk * 16 + b_coff) * 2));
#pragma unroll
                for (int i = 0; i < MT; i++) mma16816(acc_h[i][2 * jp],     a[i], b[0], b[1]);
#pragma unroll
                for (int i = 0; i < MT; i++) mma16816(acc_h[i][2 * jp + 1], a[i], b[2], b[3]);
            }
#pragma unroll
            for (int jp = 0; jp < NT / 2; jp++) {
                uint32_t b[4];
                ldsm_x4(b, bs_u +
                    (uint32_t)((((buf * 2 + 1) * BN + wn0 + jp * 16 + b_roff) * BKP
                                + kk * 16 + b_coff) * 2));
#pragma unroll
                for (int i = 0; i < MT; i++) mma16816(acc_l[i][2 * jp],     a[i], b[0], b[1]);
#pragma unroll
                for (int i = 0; i < MT; i++) mma16816(acc_l[i][2 * jp + 1], a[i], b[2], b[3]);
            }
        }
        __syncthreads();
    }

    const int grp = lane >> 2, q = lane & 3;
#pragma unroll
    for (int i = 0; i < MT; i++) {
#pragma unroll
        for (int j = 0; j < NT; j++) {
            int row0 = bm0 + wm0 + i * 16 + grp;
            int row1 = row0 + 8;
            int col  = bn0 + wn0 + j * 8 + q * 2;
            float bv0 = bias[col];
            float bv1 = bias[col + 1];
            float v00 = fmaf(acc_l[i][j][0], LO_INV_SCALE, acc_h[i][j][0]) + bv0;
            float v01 = fmaf(acc_l[i][j][1], LO_INV_SCALE, acc_h[i][j][1]) + bv1;
            float v10 = fmaf(acc_l[i][j][2], LO_INV_SCALE, acc_h[i][j][2]) + bv0;
            float v11 = fmaf(acc_l[i][j][3], LO_INV_SCALE, acc_h[i][j][3]) + bv1;
            *(float2*)&C[(size_t)row0 * N + col] = make_float2(v00, v01);
            *(float2*)&C[(size_t)row1 * N + col] = make_float2(v10, v11);
        }
    }
}

// ====== GEMM2 (bit-packed A): FROZEN round-14 config (structural plateau ~99us) ======
#define G2_BM 64
#define G2_BK 64
#define G2_BKP 72
__global__ void __launch_bounds__(128, 4)
gemm2_bits(const uint32_t* __restrict__ Abits,
           const __half* __restrict__ Whi,
           const __half* __restrict__ Wlo,
           const float* __restrict__ bias,
           float* __restrict__ C,
           int M, int N, int K)
{
    constexpr int BM = G2_BM, BN = 64, BK = G2_BK, BKP = G2_BKP;
    constexpr int MT = 2, NT = 4;               // WM=32, WN=32
    constexpr int KCH = BK / 8;                 // 8
    constexpr int BCH = BN * KCH;               // 512

    extern __shared__ __align__(16) unsigned char smem_raw[];
    __half* As = reinterpret_cast<__half*>(smem_raw);   // [2][BM][BKP]
    __half* Bs = As + 2 * BM * BKP;                      // [2][2][BN][BKP]

    const int tid  = threadIdx.x;
    const int wid  = tid >> 5;                  // 0..3
    const int lane = tid & 31;

    const int wm0 = (wid & 1) * 32;
    const int wn0 = (wid >> 1) * 32;
    const int bm0 = blockIdx.y * BM;
    const int NK  = K / BK;
    const int KW  = K >> 5;

    const int mi = lane >> 3, rr = lane & 7;
    const int a_roff = (mi & 1) * 8 + rr;
    const int a_coff = (mi >> 1) * 8;
    const int b_roff = (mi >> 1) * 8 + rr;
    const int b_coff = (mi & 1) * 8;

    const uint32_t as_u = (uint32_t)__cvta_generic_to_shared(As);
    const uint32_t bs_u = (uint32_t)__cvta_generic_to_shared(Bs);

    float acc_h[MT][NT][4];
    float acc_l[MT][NT][4];
#pragma unroll
    for (int i = 0; i < MT; i++)
#pragma unroll
        for (int j = 0; j < NT; j++)
#pragma unroll
            for (int e = 0; e < 4; e++) { acc_h[i][j][e] = 0.f; acc_l[i][j][e] = 0.f; }

    auto load_stage = [&](int stage, int kt) {
        const int k0 = kt * BK;
        {
            int row = tid >> 1, half = tid & 1;
            uint32_t w = Abits[(size_t)(bm0 + row) * KW + (kt << 1) + half];
            __half* dst = &As[(stage * BM + row) * BKP + half * 32];
#pragma unroll
            for (int g = 0; g < 8; g++) {
                uint32_t b4 = w >> (4 * g);
                uint32_t lo = ((b4 & 1) * 0x3C00u) | (((b4 >> 1) & 1) * 0x3C000000u);
                uint32_t hi = (((b4 >> 2) & 1) * 0x3C00u) | (((b4 >> 3) & 1) * 0x3C000000u);
                *(uint2*)(dst + g * 4) = make_uint2(lo, hi);
            }
        }
#pragma unroll
        for (int c = tid; c < BCH; c += 128) {
            int row = c / KCH, kc = (c % KCH) * 8;
            size_t g = (size_t)row * K + k0 + kc;
            cp16(&Bs[((stage * 2 + 0) * BN + row) * BKP + kc], Whi + g);
            cp16(&Bs[((stage * 2 + 1) * BN + row) * BKP + kc], Wlo + g);
        }
    };

    load_stage(0, 0);
    cp_commit();

    for (int kt = 0; kt < NK; kt++) {
        const int buf = kt & 1;
        if (kt + 1 < NK) {
            load_stage(buf ^ 1, kt + 1);
            cp_commit();
            cp_wait1();
        } else {
            cp_wait0();
        }
        __syncthreads();

#pragma unroll
        for (int kk = 0; kk < BK / 16; kk++) {
            uint32_t a[MT][4];
#pragma unroll
            for (int i = 0; i < MT; i++)
                ldsm_x4(a[i], as_u +
                    (uint32_t)(((buf * BM + wm0 + i * 16 + a_roff) * BKP
                                + kk * 16 + a_coff) * 2));
#pragma unroll
            for (int jp = 0; jp < NT / 2; jp++) {
                uint32_t b[4];
                ldsm_x4(b, bs_u +
                    (uint32_t)((((buf * 2 + 0) * BN + wn0 + jp * 16 + b_roff) * BKP
                                + kk * 16 + b_coff) * 2));
#pragma unroll
                for (int i = 0; i < MT; i++) mma16816(acc_h[i][2 * jp],     a[i], b[0], b[1]);
#pragma unroll
                for (int i = 0; i < MT; i++) mma16816(acc_h[i][2 * jp + 1], a[i], b[2], b[3]);
            }
#pragma unroll
            for (int jp = 0; jp < NT / 2; jp++) {
                uint32_t b[4];
                ldsm_x4(b, bs_u +
                    (uint32_t)((((buf * 2 + 1) * BN + wn0 + jp * 16 + b_roff) * BKP
                                + kk * 16 + b_coff) * 2));
#pragma unroll
                for (int i = 0; i < MT; i++) mma16816(acc_l[i][2 * jp],     a[i], b[0], b[1]);
#pragma unroll
                for (int i = 0; i < MT; i++) mma16816(acc_l[i][2 * jp + 1], a[i], b[2], b[3]);
            }
        }
        __syncthreads();
    }

    const int grp = lane >> 2, q = lane & 3;
#pragma unroll
    for (int i = 0; i < MT; i++) {
#pragma unroll
        for (int j = 0; j < NT; j++) {
            int row0 = bm0 + wm0 + i * 16 + grp;
            int row1 = row0 + 8;
            int col  = wn0 + j * 8 + q * 2;
            float bv0 = bias[col];
            float bv1 = bias[col + 1];
            float v00 = fmaf(acc_l[i][j][0], LO_INV_SCALE, acc_h[i][j][0]) + bv0;
            float v01 = fmaf(acc_l[i][j][1], LO_INV_SCALE, acc_h[i][j][1]) + bv1;
            float v10 = fmaf(acc_l[i][j][2], LO_INV_SCALE, acc_h[i][j][2]) + bv0;
            float v11 = fmaf(acc_l[i][j][3], LO_INV_SCALE, acc_h[i][j][3]) + bv1;
            *(float2*)&C[(size_t)row0 * N + col] = make_float2(v00, v01);
            *(float2*)&C[(size_t)row1 * N + col] = make_float2(v10, v11);
        }
    }
}

// ============ LIF layer 1 (4-wide): currents -> bit-packed spikes ============
// Each warp covers 128 h of one b: thread handles h = hb + 32*j + lane (j=0..3),
// giving MLP=4 on the cur1 stream. Four ballots -> one uint4 (16B) spike store.
// Per-neuron op order identical to scalar version (_rn ops, no FMA fusion).
__global__ void lif1_kernel(const float* __restrict__ cur, uint32_t* __restrict__ spkb) {
    int gw   = (blockIdx.x * blockDim.x + threadIdx.x) >> 5;  // warp id: 32768 total
    int lane = threadIdx.x & 31;
    int b  = gw >> 5;                 // 32 warps per batch row
    int hb = (gw & 31) << 7;          // 128 h per warp
    const size_t base = (size_t)b * HID_DIM + hb + lane;

    float mem0 = 0.f, mem1 = 0.f, mem2 = 0.f, mem3 = 0.f;
    float sp0 = 0.f, sp1 = 0.f, sp2 = 0.f, sp3 = 0.f;
#pragma unroll
    for (int t = 0; t < T_STEPS; t++) {
        const float* p = cur + (size_t)t * BATCH * HID_DIM + base;
        float c0 = p[0], c1 = p[32], c2 = p[64], c3 = p[96];
        mem0 = __fsub_rn(__fadd_rn(__fmul_rn(0.9f, mem0), c0), sp0);
        mem1 = __fsub_rn(__fadd_rn(__fmul_rn(0.9f, mem1), c1), sp1);
        mem2 = __fsub_rn(__fadd_rn(__fmul_rn(0.9f, mem2), c2), sp2);
        mem3 = __fsub_rn(__fadd_rn(__fmul_rn(0.9f, mem3), c3), sp3);
        sp0 = (mem0 > 1.0f) ? 1.f : 0.f;
        sp1 = (mem1 > 1.0f) ? 1.f : 0.f;
        sp2 = (mem2 > 1.0f) ? 1.f : 0.f;
        sp3 = (mem3 > 1.0f) ? 1.f : 0.f;
        uint32_t w0 = __ballot_sync(0xFFFFFFFFu, mem0 > 1.0f);
        uint32_t w1 = __ballot_sync(0xFFFFFFFFu, mem1 > 1.0f);
        uint32_t w2 = __ballot_sync(0xFFFFFFFFu, mem2 > 1.0f);
        uint32_t w3 = __ballot_sync(0xFFFFFFFFu, mem3 > 1.0f);
        if (lane == 0) {
            uint4 st = make_uint4(w0, w1, w2, w3);
            *(uint4*)&spkb[(size_t)(t * BATCH + b) * HIDW + (hb >> 5)] = st;
        }
    }
}

// ======================= LIF layer 2: currents -> spike counts =======================
__global__ void lif2_kernel(const float* __restrict__ cur, float* __restrict__ out) {
    int idx = blockIdx.x * blockDim.x + threadIdx.x;   // = b*OUT + o
    if (idx >= BATCH * OUT_DIM) return;
    float mem = 0.f, sp = 0.f, cnt = 0.f;
#pragma unroll
    for (int t = 0; t < T_STEPS; t++) {
        float c = cur[(size_t)t * BATCH * OUT_DIM + idx];
        mem = __fsub_rn(__fadd_rn(__fmul_rn(0.9f, mem), c), sp);
        sp  = (mem > 1.0f) ? 1.f : 0.f;
        cnt += sp;
    }
    out[idx] = cnt;
}

// ======================= launch =======================
extern "C" void kernel_launch(void* const* d_in, const int* in_sizes, int n_in,
                              void* d_out, int out_size) {
    const float* x  = (const float*)d_in[0];   // [25,1024,1024]
    const float* w1 = (const float*)d_in[1];   // [4096,1024]
    const float* b1 = (const float*)d_in[2];   // [4096]
    const float* w2 = (const float*)d_in[3];   // [64,4096]
    const float* b2 = (const float*)d_in[4];   // [64]
    float* out = (float*)d_out;                // [1024,64]

    __half *A, *w1hi, *w1lo, *w2hi, *w2lo;
    uint32_t* spkb;
    float *cur1, *cur2;
    cudaGetSymbolAddress((void**)&A,    g_A);
    cudaGetSymbolAddress((void**)&w1hi, g_w1hi);
    cudaGetSymbolAddress((void**)&w1lo, g_w1lo);
    cudaGetSymbolAddress((void**)&w2hi, g_w2hi);
    cudaGetSymbolAddress((void**)&w2lo, g_w2lo);
    cudaGetSymbolAddress((void**)&spkb, g_spkb);
    cudaGetSymbolAddress((void**)&cur1, g_cur1);
    cudaGetSymbolAddress((void**)&cur2, g_cur2);

    constexpr int SMEM1 = 2 * (128 * 72 + 2 * 64 * 72) * 2;   // 73728 B
    constexpr int SMEM2 = 2 * (64 * 72 + 2 * 64 * 72) * 2;    // 55296 B
    cudaFuncSetAttribute((const void*)gemm_hilo<128, 64, 64, 32, 32, 2>,
                         cudaFuncAttributeMaxDynamicSharedMemorySize, SMEM1);
    cudaFuncSetAttribute((const void*)gemm2_bits,
                         cudaFuncAttributeMaxDynamicSharedMemorySize, SMEM2);

    // 1) merged prep (vectorized, single launch)
    k_prep<<<4096, 256>>>((const float4*)x, (uint2*)A,
                          (const float4*)w1, (uint2*)w1hi, (uint2*)w1lo,
                          (const float4*)w2, (uint2*)w2hi, (uint2*)w2lo);

    // 2) GEMM1: cur1[25600,4096] = A[25600,1024] @ w1^T + b1  (grid 64x200, FROZEN)
    gemm_hilo<128, 64, 64, 32, 32, 2>
        <<<dim3(HID_DIM / 64, M_ROWS / 128), 256, SMEM1>>>(
            A, w1hi, w1lo, b1, cur1, M_ROWS, HID_DIM, IN_DIM);

    // 3) LIF layer 1 (4-wide) -> bit-packed spikes: 32768 warps = 4096 blocks
    lif1_kernel<<<4096, 256>>>(cur1, spkb);

    // 4) GEMM2: cur2[25600,64] = spikes @ w2^T + b2  (grid 1x400, FROZEN)
    gemm2_bits<<<dim3(1, M_ROWS / G2_BM), 128, SMEM2>>>(
        spkb, w2hi, w2lo, b2, cur2, M_ROWS, OUT_DIM, HID_DIM);

    // 5) LIF layer 2 + spike counting
    lif2_kernel<<<(BATCH * OUT_DIM) / 256, 256>>>(cur2, out);
}

// round 16
// speedup vs baseline: 1.3422x; 1.0060x over previous
#include <cuda_runtime.h>
#include <cuda_fp16.h>
#include <cstdint>
#include <cstddef>

// ======================= problem dims (fixed) =======================
#define T_STEPS 25
#define BATCH   1024
#define IN_DIM  1024
#define HID_DIM 4096
#define OUT_DIM 64
#define M_ROWS  (T_STEPS * BATCH)   // 25600
#define HIDW    (HID_DIM / 32)      // 128 bit-words per row

#define LO_SCALE     1024.0f
#define LO_INV_SCALE 0.0009765625f  // exact 2^-10

// ======================= static device scratch =======================
__device__ __half   g_A    [(size_t)M_ROWS * IN_DIM];     // fp16 input spikes (exact 0/1)
__device__ __half   g_w1hi [(size_t)HID_DIM * IN_DIM];
__device__ __half   g_w1lo [(size_t)HID_DIM * IN_DIM];    // (w - hi) * 1024, fp16-normal
__device__ __half   g_w2hi [(size_t)OUT_DIM * HID_DIM];
__device__ __half   g_w2lo [(size_t)OUT_DIM * HID_DIM];
__device__ float    g_cur1 [(size_t)M_ROWS * HID_DIM];    // layer-1 currents
__device__ uint32_t g_spkb [(size_t)M_ROWS * HIDW];       // layer-1 spikes, bit-packed
__device__ float    g_cur2 [(size_t)M_ROWS * OUT_DIM];    // layer-2 currents

// ======================= helpers =======================
__device__ __forceinline__ void cp16(void* dst_smem, const void* src_gmem) {
    uint32_t d = (uint32_t)__cvta_generic_to_shared(dst_smem);
    asm volatile("cp.async.cg.shared.global [%0], [%1], 16;" :: "r"(d), "l"(src_gmem));
}
__device__ __forceinline__ void cp_commit() { asm volatile("cp.async.commit_group;"); }
__device__ __forceinline__ void cp_wait1()  { asm volatile("cp.async.wait_group 1;"); }
__device__ __forceinline__ void cp_wait0()  { asm volatile("cp.async.wait_group 0;"); }

__device__ __forceinline__ void ldsm_x4(uint32_t* r, uint32_t saddr) {
    asm volatile("ldmatrix.sync.aligned.m8n8.x4.shared.b16 {%0,%1,%2,%3}, [%4];"
        : "=r"(r[0]), "=r"(r[1]), "=r"(r[2]), "=r"(r[3]) : "r"(saddr));
}

__device__ __forceinline__ void mma16816(float* c, const uint32_t* a, uint32_t b0, uint32_t b1) {
    asm volatile(
        "mma.sync.aligned.m16n8k16.row.col.f32.f16.f16.f32 "
        "{%0,%1,%2,%3}, {%4,%5,%6,%7}, {%8,%9}, {%0,%1,%2,%3};"
        : "+f"(c[0]), "+f"(c[1]), "+f"(c[2]), "+f"(c[3])
        : "r"(a[0]), "r"(a[1]), "r"(a[2]), "r"(a[3]), "r"(b0), "r"(b1));
}

__device__ __forceinline__ uint32_t h2bits(__half2 h) {
    return *reinterpret_cast<uint32_t*>(&h);
}

// ======================= merged prep kernel (vectorized, bit-identical) ===============
#define N_CVT (M_ROWS * IN_DIM)       // 26214400
#define N_W1  (HID_DIM * IN_DIM)      // 4194304
#define N_W2  (OUT_DIM * HID_DIM)     // 262144
__global__ void k_prep(const float4* __restrict__ x, uint2* __restrict__ A,
                       const float4* __restrict__ w1, uint2* __restrict__ w1hi,
                       uint2* __restrict__ w1lo,
                       const float4* __restrict__ w2, uint2* __restrict__ w2hi,
                       uint2* __restrict__ w2lo) {
    const int nc = N_CVT / 4, n1 = N_W1 / 4, n2 = N_W2 / 4;
    const int total = nc + n1 + n2;
    for (int i = blockIdx.x * blockDim.x + threadIdx.x; i < total;
         i += gridDim.x * blockDim.x) {
        if (i < nc) {
            float4 v = x[i];
            A[i] = make_uint2(h2bits(__floats2half2_rn(v.x, v.y)),
                              h2bits(__floats2half2_rn(v.z, v.w)));
        } else {
            const float4* w; uint2 *hi, *lo; int j;
            if (i < nc + n1) { j = i - nc; w = w1; hi = w1hi; lo = w1lo; }
            else             { j = i - nc - n1; w = w2; hi = w2hi; lo = w2lo; }
            float4 v = w[j];
            __half h0 = __float2half_rn(v.x), h1 = __float2half_rn(v.y);
            __half h2 = __float2half_rn(v.z), h3 = __float2half_rn(v.w);
            hi[j] = make_uint2(h2bits(__halves2half2(h0, h1)),
                               h2bits(__halves2half2(h2, h3)));
            lo[j] = make_uint2(
                h2bits(__floats2half2_rn(
                    __fmul_rn(__fsub_rn(v.x, __half2float(h0)), LO_SCALE),
                    __fmul_rn(__fsub_rn(v.y, __half2float(h1)), LO_SCALE))),
                h2bits(__floats2half2_rn(
                    __fmul_rn(__fsub_rn(v.z, __half2float(h2)), LO_SCALE),
                    __fmul_rn(__fsub_rn(v.w, __half2float(h3)), LO_SCALE))));
        }
    }
}

// ====== GEMM1: C[M,N] = A[M,K] @ (Whi + Wlo/1024)[N,K]^T + bias (two-plane accum) ======
// FROZEN optimum (round 5). 2-stage cp.async; ldmatrix.x4; separate fp32 accumulators
// per plane, combined as acc_hi + acc_lo/1024 + bias in the epilogue.
template <int BM, int BN, int BK, int WM, int WN, int MINCTA>
__global__ void __launch_bounds__((BM / WM) * (BN / WN) * 32, MINCTA)
gemm_hilo(const __half* __restrict__ A,
          const __half* __restrict__ Whi,
          const __half* __restrict__ Wlo,
          const float* __restrict__ bias,
          float* __restrict__ C,
          int M, int N, int K)
{
    constexpr int BKP  = BK + 8;
    constexpr int NW   = (BM / WM) * (BN / WN);
    constexpr int NTH  = NW * 32;
    constexpr int MT   = WM / 16;
    constexpr int NT   = WN / 8;
    constexpr int KCH  = BK / 8;
    constexpr int ACH  = BM * KCH;
    constexpr int BCH  = BN * KCH;

    extern __shared__ __align__(16) unsigned char smem_raw[];
    __half* As = reinterpret_cast<__half*>(smem_raw);   // [2][BM][BKP]
    __half* Bs = As + 2 * BM * BKP;                      // [2][2][BN][BKP]

    const int tid  = threadIdx.x;
    const int wid  = tid >> 5;
    const int lane = tid & 31;

    const int wm0 = (wid % (BM / WM)) * WM;
    const int wn0 = (wid / (BM / WM)) * WN;
    const int bm0 = blockIdx.y * BM;
    const int bn0 = blockIdx.x * BN;
    const int NK  = K / BK;

    const int mi = lane >> 3, rr = lane & 7;
    const int a_roff = (mi & 1) * 8 + rr;
    const int a_coff = (mi >> 1) * 8;
    const int b_roff = (mi >> 1) * 8 + rr;
    const int b_coff = (mi & 1) * 8;

    const uint32_t as_u = (uint32_t)__cvta_generic_to_shared(As);
    const uint32_t bs_u = (uint32_t)__cvta_generic_to_shared(Bs);

    float acc_h[MT][NT][4];
    float acc_l[MT][NT][4];
#pragma unroll
    for (int i = 0; i < MT; i++)
#pragma unroll
        for (int j = 0; j < NT; j++)
#pragma unroll
            for (int e = 0; e < 4; e++) { acc_h[i][j][e] = 0.f; acc_l[i][j][e] = 0.f; }

    auto load_stage = [&](int stage, int kt) {
        const int k0 = kt * BK;
#pragma unroll
        for (int c = tid; c < ACH; c += NTH) {
            int row = c / KCH, kc = (c % KCH) * 8;
            cp16(&As[(stage * BM + row) * BKP + kc],
                 A + (size_t)(bm0 + row) * K + k0 + kc);
        }
#pragma unroll
        for (int c = tid; c < BCH; c += NTH) {
            int row = c / KCH, kc = (c % KCH) * 8;
            size_t g = (size_t)(bn0 + row) * K + k0 + kc;
            cp16(&Bs[((stage * 2 + 0) * BN + row) * BKP + kc], Whi + g);
            cp16(&Bs[((stage * 2 + 1) * BN + row) * BKP + kc], Wlo + g);
        }
    };

    load_stage(0, 0);
    cp_commit();

    for (int kt = 0; kt < NK; kt++) {
        const int buf = kt & 1;
        if (kt + 1 < NK) {
            load_stage(buf ^ 1, kt + 1);
            cp_commit();
            cp_wait1();
        } else {
            cp_wait0();
        }
        __syncthreads();

#pragma unroll
        for (int kk = 0; kk < BK / 16; kk++) {
            uint32_t a[MT][4];
#pragma unroll
            for (int i = 0; i < MT; i++)
                ldsm_x4(a[i], as_u +
                    (uint32_t)(((buf * BM + wm0 + i * 16 + a_roff) * BKP
                                + kk * 16 + a_coff) * 2));
#pragma unroll
            for (int jp = 0; jp < NT / 2; jp++) {
                uint32_t b[4];
                ldsm_x4(b, bs_u +
                    (uint32_t)((((buf * 2 + 0) * BN + wn0 + jp * 16 + b_roff) * BKP
                                + kk * 16 + b_coff) * 2));
#pragma unroll
                for (int i = 0; i < MT; i++) mma16816(acc_h[i][2 * jp],     a[i], b[0], b[1]);
#pragma unroll
                for (int i = 0; i < MT; i++) mma16816(acc_h[i][2 * jp + 1], a[i], b[2], b[3]);
            }
#pragma unroll
            for (int jp = 0; jp < NT / 2; jp++) {
                uint32_t b[4];
                ldsm_x4(b, bs_u +
                    (uint32_t)((((buf * 2 + 1) * BN + wn0 + jp * 16 + b_roff) * BKP
                                + kk * 16 + b_coff) * 2));
#pragma unroll
                for (int i = 0; i < MT; i++) mma16816(acc_l[i][2 * jp],     a[i], b[0], b[1]);
#pragma unroll
                for (int i = 0; i < MT; i++) mma16816(acc_l[i][2 * jp + 1], a[i], b[2], b[3]);
            }
        }
        __syncthreads();
    }

    const int grp = lane >> 2, q = lane & 3;
#pragma unroll
    for (int i = 0; i < MT; i++) {
#pragma unroll
        for (int j = 0; j < NT; j++) {
            int row0 = bm0 + wm0 + i * 16 + grp;
            int row1 = row0 + 8;
            int col  = bn0 + wn0 + j * 8 + q * 2;
            float bv0 = bias[col];
            float bv1 = bias[col + 1];
            float v00 = fmaf(acc_l[i][j][0], LO_INV_SCALE, acc_h[i][j][0]) + bv0;
            float v01 = fmaf(acc_l[i][j][1], LO_INV_SCALE, acc_h[i][j][1]) + bv1;
            float v10 = fmaf(acc_l[i][j][2], LO_INV_SCALE, acc_h[i][j][2]) + bv0;
            float v11 = fmaf(acc_l[i][j][3], LO_INV_SCALE, acc_h[i][j][3]) + bv1;
            *(float2*)&C[(size_t)row0 * N + col] = make_float2(v00, v01);
            *(float2*)&C[(size_t)row1 * N + col] = make_float2(v10, v11);
        }
    }
}

// ====== GEMM2 (bit-packed A): C[M,64] = spikes[M,K] @ (Whi + Wlo/1024)^T + bias ======
// Round-14 tiling (BM=64, BK=64, 4 warps, WM=WN=32) with two changes:
//   1. __launch_bounds__(128,3): 3 CTAs/SM actually fit (4 never did: RF-full);
//      declaring 3 frees ~40 regs/thread for scheduling. One wave kept (444 >= 400).
//   2. Spike-bit word software-prefetched one iteration ahead into a register,
//      removing the synchronous LDG->expand stall from the NK=64 loop body.
#define G2_BM 64
#define G2_BK 64
#define G2_BKP 72
__global__ void __launch_bounds__(128, 3)
gemm2_bits(const uint32_t* __restrict__ Abits,
           const __half* __restrict__ Whi,
           const __half* __restrict__ Wlo,
           const float* __restrict__ bias,
           float* __restrict__ C,
           int M, int N, int K)
{
    constexpr int BM = G2_BM, BN = 64, BK = G2_BK, BKP = G2_BKP;
    constexpr int MT = 2, NT = 4;               // WM=32, WN=32
    constexpr int KCH = BK / 8;                 // 8
    constexpr int BCH = BN * KCH;               // 512

    extern __shared__ __align__(16) unsigned char smem_raw[];
    __half* As = reinterpret_cast<__half*>(smem_raw);   // [2][BM][BKP]
    __half* Bs = As + 2 * BM * BKP;                      // [2][2][BN][BKP]

    const int tid  = threadIdx.x;
    const int wid  = tid >> 5;                  // 0..3
    const int lane = tid & 31;

    const int wm0 = (wid & 1) * 32;
    const int wn0 = (wid >> 1) * 32;
    const int bm0 = blockIdx.y * BM;
    const int NK  = K / BK;
    const int KW  = K >> 5;

    const int mi = lane >> 3, rr = lane & 7;
    const int a_roff = (mi & 1) * 8 + rr;
    const int a_coff = (mi >> 1) * 8;
    const int b_roff = (mi >> 1) * 8 + rr;
    const int b_coff = (mi & 1) * 8;

    const uint32_t as_u = (uint32_t)__cvta_generic_to_shared(As);
    const uint32_t bs_u = (uint32_t)__cvta_generic_to_shared(Bs);

    // per-thread A-bit addressing: row = tid>>1, half-word = tid&1
    const int arow = tid >> 1, ahalf = tid & 1;
    const size_t abase = (size_t)(bm0 + arow) * KW + ahalf;   // + 2*kt per stage
    __half* const adst0 = &As[arow * BKP + ahalf * 32];       // stage 0 base

    auto expand_bits = [&](int stage, uint32_t w) {
        __half* dst = adst0 + stage * BM * BKP;
#pragma unroll
        for (int g = 0; g < 8; g++) {
            uint32_t b4 = w >> (4 * g);
            uint32_t lo = ((b4 & 1) * 0x3C00u) | (((b4 >> 1) & 1) * 0x3C000000u);
            uint32_t hi = (((b4 >> 2) & 1) * 0x3C00u) | (((b4 >> 3) & 1) * 0x3C000000u);
            *(uint2*)(dst + g * 4) = make_uint2(lo, hi);
        }
    };
    auto load_b = [&](int stage, int kt) {
        const int k0 = kt * BK;
#pragma unroll
        for (int c = tid; c < BCH; c += 128) {
            int row = c / KCH, kc = (c % KCH) * 8;
            size_t g = (size_t)row * K + k0 + kc;
            cp16(&Bs[((stage * 2 + 0) * BN + row) * BKP + kc], Whi + g);
            cp16(&Bs[((stage * 2 + 1) * BN + row) * BKP + kc], Wlo + g);
        }
    };

    float acc_h[MT][NT][4];
    float acc_l[MT][NT][4];
#pragma unroll
    for (int i = 0; i < MT; i++)
#pragma unroll
        for (int j = 0; j < NT; j++)
#pragma unroll
            for (int e = 0; e < 4; e++) { acc_h[i][j][e] = 0.f; acc_l[i][j][e] = 0.f; }

    // prologue: stage 0 expanded + B in flight; bits for kt=1 prefetched
    expand_bits(0, Abits[abase]);
    load_b(0, 0);
    cp_commit();
    uint32_t w_next = Abits[abase + 2];   // bits for kt=1 (NK >= 2 always: K=4096)

    for (int kt = 0; kt < NK; kt++) {
        const int buf = kt & 1;
        if (kt + 1 < NK) {
            expand_bits(buf ^ 1, w_next);                       // no LDG stall: preloaded
            load_b(buf ^ 1, kt + 1);
            w_next = (kt + 2 < NK) ? Abits[abase + 2 * (size_t)(kt + 2)] : 0u;
            cp_commit();
            cp_wait1();
        } else {
            cp_wait0();
        }
        __syncthreads();

#pragma unroll
        for (int kk = 0; kk < BK / 16; kk++) {
            uint32_t a[MT][4];
#pragma unroll
            for (int i = 0; i < MT; i++)
                ldsm_x4(a[i], as_u +
                    (uint32_t)(((buf * BM + wm0 + i * 16 + a_roff) * BKP
                                + kk * 16 + a_coff) * 2));
#pragma unroll
            for (int jp = 0; jp < NT / 2; jp++) {
                uint32_t b[4];
                ldsm_x4(b, bs_u +
                    (uint32_t)((((buf * 2 + 0) * BN + wn0 + jp * 16 + b_roff) * BKP
                                + kk * 16 + b_coff) * 2));
#pragma unroll
                for (int i = 0; i < MT; i++) mma16816(acc_h[i][2 * jp],     a[i], b[0], b[1]);
#pragma unroll
                for (int i = 0; i < MT; i++) mma16816(acc_h[i][2 * jp + 1], a[i], b[2], b[3]);
            }
#pragma unroll
            for (int jp = 0; jp < NT / 2; jp++) {
                uint32_t b[4];
                ldsm_x4(b, bs_u +
                    (uint32_t)((((buf * 2 + 1) * BN + wn0 + jp * 16 + b_roff) * BKP
                                + kk * 16 + b_coff) * 2));
#pragma unroll
                for (int i = 0; i < MT; i++) mma16816(acc_l[i][2 * jp],     a[i], b[0], b[1]);
#pragma unroll
                for (int i = 0; i < MT; i++) mma16816(acc_l[i][2 * jp + 1], a[i], b[2], b[3]);
            }
        }
        __syncthreads();
    }

    const int grp = lane >> 2, q = lane & 3;
#pragma unroll
    for (int i = 0; i < MT; i++) {
#pragma unroll
        for (int j = 0; j < NT; j++) {
            int row0 = bm0 + wm0 + i * 16 + grp;
            int row1 = row0 + 8;
            int col  = wn0 + j * 8 + q * 2;
            float bv0 = bias[col];
            float bv1 = bias[col + 1];
            float v00 = fmaf(acc_l[i][j][0], LO_INV_SCALE, acc_h[i][j][0]) + bv0;
            float v01 = fmaf(acc_l[i][j][1], LO_INV_SCALE, acc_h[i][j][1]) + bv1;
            float v10 = fmaf(acc_l[i][j][2], LO_INV_SCALE, acc_h[i][j][2]) + bv0;
            float v11 = fmaf(acc_l[i][j][3], LO_INV_SCALE, acc_h[i][j][3]) + bv1;
            *(float2*)&C[(size_t)row0 * N + col] = make_float2(v00, v01);
            *(float2*)&C[(size_t)row1 * N + col] = make_float2(v10, v11);
        }
    }
}

// ============ LIF layer 1 (4-wide): currents -> bit-packed spikes ============
__global__ void lif1_kernel(const float* __restrict__ cur, uint32_t* __restrict__ spkb) {
    int gw   = (blockIdx.x * blockDim.x + threadIdx.x) >> 5;  // warp id: 32768 total
    int lane = threadIdx.x & 31;
    int b  = gw >> 5;                 // 32 warps per batch row
    int hb = (gw & 31) << 7;          // 128 h per warp
    const size_t base = (size_t)b * HID_DIM + hb + lane;

    float mem0 = 0.f, mem1 = 0.f, mem2 = 0.f, mem3 = 0.f;
    float sp0 = 0.f, sp1 = 0.f, sp2 = 0.f, sp3 = 0.f;
#pragma unroll
    for (int t = 0; t < T_STEPS; t++) {
        const float* p = cur + (size_t)t * BATCH * HID_DIM + base;
        float c0 = p[0], c1 = p[32], c2 = p[64], c3 = p[96];
        mem0 = __fsub_rn(__fadd_rn(__fmul_rn(0.9f, mem0), c0), sp0);
        mem1 = __fsub_rn(__fadd_rn(__fmul_rn(0.9f, mem1), c1), sp1);
        mem2 = __fsub_rn(__fadd_rn(__fmul_rn(0.9f, mem2), c2), sp2);
        mem3 = __fsub_rn(__fadd_rn(__fmul_rn(0.9f, mem3), c3), sp3);
        sp0 = (mem0 > 1.0f) ? 1.f : 0.f;
        sp1 = (mem1 > 1.0f) ? 1.f : 0.f;
        sp2 = (mem2 > 1.0f) ? 1.f : 0.f;
        sp3 = (mem3 > 1.0f) ? 1.f : 0.f;
        uint32_t w0 = __ballot_sync(0xFFFFFFFFu, mem0 > 1.0f);
        uint32_t w1 = __ballot_sync(0xFFFFFFFFu, mem1 > 1.0f);
        uint32_t w2 = __ballot_sync(0xFFFFFFFFu, mem2 > 1.0f);
        uint32_t w3 = __ballot_sync(0xFFFFFFFFu, mem3 > 1.0f);
        if (lane == 0) {
            uint4 st = make_uint4(w0, w1, w2, w3);
            *(uint4*)&spkb[(size_t)(t * BATCH + b) * HIDW + (hb >> 5)] = st;
        }
    }
}

// ======================= LIF layer 2: currents -> spike counts =======================
__global__ void lif2_kernel(const float* __restrict__ cur, float* __restrict__ out) {
    int idx = blockIdx.x * blockDim.x + threadIdx.x;   // = b*OUT + o
    if (idx >= BATCH * OUT_DIM) return;
    float mem = 0.f, sp = 0.f, cnt = 0.f;
#pragma unroll
    for (int t = 0; t < T_STEPS; t++) {
        float c = cur[(size_t)t * BATCH * OUT_DIM + idx];
        mem = __fsub_rn(__fadd_rn(__fmul_rn(0.9f, mem), c), sp);
        sp  = (mem > 1.0f) ? 1.f : 0.f;
        cnt += sp;
    }
    out[idx] = cnt;
}

// ======================= launch =======================
extern "C" void kernel_launch(void* const* d_in, const int* in_sizes, int n_in,
                              void* d_out, int out_size) {
    const float* x  = (const float*)d_in[0];   // [25,1024,1024]
    const float* w1 = (const float*)d_in[1];   // [4096,1024]
    const float* b1 = (const float*)d_in[2];   // [4096]
    const float* w2 = (const float*)d_in[3];   // [64,4096]
    const float* b2 = (const float*)d_in[4];   // [64]
    float* out = (float*)d_out;                // [1024,64]

    __half *A, *w1hi, *w1lo, *w2hi, *w2lo;
    uint32_t* spkb;
    float *cur1, *cur2;
    cudaGetSymbolAddress((void**)&A,    g_A);
    cudaGetSymbolAddress((void**)&w1hi, g_w1hi);
    cudaGetSymbolAddress((void**)&w1lo, g_w1lo);
    cudaGetSymbolAddress((void**)&w2hi, g_w2hi);
    cudaGetSymbolAddress((void**)&w2lo, g_w2lo);
    cudaGetSymbolAddress((void**)&spkb, g_spkb);
    cudaGetSymbolAddress((void**)&cur1, g_cur1);
    cudaGetSymbolAddress((void**)&cur2, g_cur2);

    constexpr int SMEM1 = 2 * (128 * 72 + 2 * 64 * 72) * 2;   // 73728 B
    constexpr int SMEM2 = 2 * (64 * 72 + 2 * 64 * 72) * 2;    // 55296 B
    cudaFuncSetAttribute((const void*)gemm_hilo<128, 64, 64, 32, 32, 2>,
                         cudaFuncAttributeMaxDynamicSharedMemorySize, SMEM1);
    cudaFuncSetAttribute((const void*)gemm2_bits,
                         cudaFuncAttributeMaxDynamicSharedMemorySize, SMEM2);

    // 1) merged prep (vectorized, single launch)
    k_prep<<<4096, 256>>>((const float4*)x, (uint2*)A,
                          (const float4*)w1, (uint2*)w1hi, (uint2*)w1lo,
                          (const float4*)w2, (uint2*)w2hi, (uint2*)w2lo);

    // 2) GEMM1: cur1[25600,4096] = A[25600,1024] @ w1^T + b1  (grid 64x200, FROZEN)
    gemm_hilo<128, 64, 64, 32, 32, 2>
        <<<dim3(HID_DIM / 64, M_ROWS / 128), 256, SMEM1>>>(
            A, w1hi, w1lo, b1, cur1, M_ROWS, HID_DIM, IN_DIM);

    // 3) LIF layer 1 (4-wide) -> bit-packed spikes
    lif1_kernel<<<4096, 256>>>(cur1, spkb);

    // 4) GEMM2: cur2[25600,64] = spikes @ w2^T + b2  (grid 1x400, prefetched bits)
    gemm2_bits<<<dim3(1, M_ROWS / G2_BM), 128, SMEM2>>>(
        spkb, w2hi, w2lo, b2, cur2, M_ROWS, OUT_DIM, HID_DIM);

    // 5) LIF layer 2 + spike counting
    lif2_kernel<<<(BATCH * OUT_DIM) / 256, 256>>>(cur2, out);
}

// round 17
// speedup vs baseline: 1.3563x; 1.0105x over previous
#include <cuda_runtime.h>
#include <cuda_fp16.h>
#include <cstdint>
#include <cstddef>

// ======================= problem dims (fixed) =======================
#define T_STEPS 25
#define BATCH   1024
#define IN_DIM  1024
#define HID_DIM 4096
#define OUT_DIM 64
#define M_ROWS  (T_STEPS * BATCH)   // 25600
#define HIDW    (HID_DIM / 32)      // 128 bit-words per row

#define LO_SCALE     1024.0f
#define LO_INV_SCALE 0.0009765625f  // exact 2^-10

// ======================= static device scratch =======================
__device__ __half   g_A    [(size_t)M_ROWS * IN_DIM];     // fp16 input spikes (exact 0/1)
__device__ __half   g_w1hi [(size_t)HID_DIM * IN_DIM];
__device__ __half   g_w1lo [(size_t)HID_DIM * IN_DIM];    // (w - hi) * 1024, fp16-normal
__device__ __half   g_w2hi [(size_t)OUT_DIM * HID_DIM];
__device__ __half   g_w2lo [(size_t)OUT_DIM * HID_DIM];
__device__ float    g_cur1 [(size_t)M_ROWS * HID_DIM];    // layer-1 currents
__device__ uint32_t g_spkb [(size_t)M_ROWS * HIDW];       // layer-1 spikes, bit-packed
__device__ float    g_cur2 [(size_t)M_ROWS * OUT_DIM];    // layer-2 currents

// ======================= helpers =======================
__device__ __forceinline__ void cp16(void* dst_smem, const void* src_gmem) {
    uint32_t d = (uint32_t)__cvta_generic_to_shared(dst_smem);
    asm volatile("cp.async.cg.shared.global [%0], [%1], 16;" :: "r"(d), "l"(src_gmem));
}
__device__ __forceinline__ void cp_commit() { asm volatile("cp.async.commit_group;"); }
__device__ __forceinline__ void cp_wait0()  { asm volatile("cp.async.wait_group 0;"); }

__device__ __forceinline__ void ldsm_x4(uint32_t* r, uint32_t saddr) {
    asm volatile("ldmatrix.sync.aligned.m8n8.x4.shared.b16 {%0,%1,%2,%3}, [%4];"
        : "=r"(r[0]), "=r"(r[1]), "=r"(r[2]), "=r"(r[3]) : "r"(saddr));
}

__device__ __forceinline__ void mma16816(float* c, const uint32_t* a, uint32_t b0, uint32_t b1) {
    asm volatile(
        "mma.sync.aligned.m16n8k16.row.col.f32.f16.f16.f32 "
        "{%0,%1,%2,%3}, {%4,%5,%6,%7}, {%8,%9}, {%0,%1,%2,%3};"
        : "+f"(c[0]), "+f"(c[1]), "+f"(c[2]), "+f"(c[3])
        : "r"(a[0]), "r"(a[1]), "r"(a[2]), "r"(a[3]), "r"(b0), "r"(b1));
}

__device__ __forceinline__ uint32_t h2bits(__half2 h) {
    return *reinterpret_cast<uint32_t*>(&h);
}

// ======================= merged prep kernel (vectorized, bit-identical) ===============
#define N_CVT (M_ROWS * IN_DIM)       // 26214400
#define N_W1  (HID_DIM * IN_DIM)      // 4194304
#define N_W2  (OUT_DIM * HID_DIM)     // 262144
__global__ void k_prep(const float4* __restrict__ x, uint2* __restrict__ A,
                       const float4* __restrict__ w1, uint2* __restrict__ w1hi,
                       uint2* __restrict__ w1lo,
                       const float4* __restrict__ w2, uint2* __restrict__ w2hi,
                       uint2* __restrict__ w2lo) {
    const int nc = N_CVT / 4, n1 = N_W1 / 4, n2 = N_W2 / 4;
    const int total = nc + n1 + n2;
    for (int i = blockIdx.x * blockDim.x + threadIdx.x; i < total;
         i += gridDim.x * blockDim.x) {
        if (i < nc) {
            float4 v = x[i];
            A[i] = make_uint2(h2bits(__floats2half2_rn(v.x, v.y)),
                              h2bits(__floats2half2_rn(v.z, v.w)));
        } else {
            const float4* w; uint2 *hi, *lo; int j;
            if (i < nc + n1) { j = i - nc; w = w1; hi = w1hi; lo = w1lo; }
            else             { j = i - nc - n1; w = w2; hi = w2hi; lo = w2lo; }
            float4 v = w[j];
            __half h0 = __float2half_rn(v.x), h1 = __float2half_rn(v.y);
            __half h2 = __float2half_rn(v.z), h3 = __float2half_rn(v.w);
            hi[j] = make_uint2(h2bits(__halves2half2(h0, h1)),
                               h2bits(__halves2half2(h2, h3)));
            lo[j] = make_uint2(
                h2bits(__floats2half2_rn(
                    __fmul_rn(__fsub_rn(v.x, __half2float(h0)), LO_SCALE),
                    __fmul_rn(__fsub_rn(v.y, __half2float(h1)), LO_SCALE))),
                h2bits(__floats2half2_rn(
                    __fmul_rn(__fsub_rn(v.z, __half2float(h2)), LO_SCALE),
                    __fmul_rn(__fsub_rn(v.w, __half2float(h3)), LO_SCALE))));
        }
    }
}

// ====== GEMM1: C[M,N] = A[M,K] @ (Whi + Wlo/1024)[N,K]^T + bias (two-plane accum) ======
// Round-5 tiling; single-sync double buffer: [wait; sync; load(kt+1); mma(kt)].
// The one barrier separates kt-1's reads of slot buf^1 from kt's writes to it AND
// publishes stage kt's data. Overlap preserved (load has the whole mma phase).
template <int BM, int BN, int BK, int WM, int WN, int MINCTA>
__global__ void __launch_bounds__((BM / WM) * (BN / WN) * 32, MINCTA)
gemm_hilo(const __half* __restrict__ A,
          const __half* __restrict__ Whi,
          const __half* __restrict__ Wlo,
          const float* __restrict__ bias,
          float* __restrict__ C,
          int M, int N, int K)
{
    constexpr int BKP  = BK + 8;
    constexpr int NW   = (BM / WM) * (BN / WN);
    constexpr int NTH  = NW * 32;
    constexpr int MT   = WM / 16;
    constexpr int NT   = WN / 8;
    constexpr int KCH  = BK / 8;
    constexpr int ACH  = BM * KCH;
    constexpr int BCH  = BN * KCH;

    extern __shared__ __align__(16) unsigned char smem_raw[];
    __half* As = reinterpret_cast<__half*>(smem_raw);   // [2][BM][BKP]
    __half* Bs = As + 2 * BM * BKP;                      // [2][2][BN][BKP]

    const int tid  = threadIdx.x;
    const int wid  = tid >> 5;
    const int lane = tid & 31;

    const int wm0 = (wid % (BM / WM)) * WM;
    const int wn0 = (wid / (BM / WM)) * WN;
    const int bm0 = blockIdx.y * BM;
    const int bn0 = blockIdx.x * BN;
    const int NK  = K / BK;

    const int mi = lane >> 3, rr = lane & 7;
    const int a_roff = (mi & 1) * 8 + rr;
    const int a_coff = (mi >> 1) * 8;
    const int b_roff = (mi >> 1) * 8 + rr;
    const int b_coff = (mi & 1) * 8;

    const uint32_t as_u = (uint32_t)__cvta_generic_to_shared(As);
    const uint32_t bs_u = (uint32_t)__cvta_generic_to_shared(Bs);

    float acc_h[MT][NT][4];
    float acc_l[MT][NT][4];
#pragma unroll
    for (int i = 0; i < MT; i++)
#pragma unroll
        for (int j = 0; j < NT; j++)
#pragma unroll
            for (int e = 0; e < 4; e++) { acc_h[i][j][e] = 0.f; acc_l[i][j][e] = 0.f; }

    auto load_stage = [&](int stage, int kt) {
        const int k0 = kt * BK;
#pragma unroll
        for (int c = tid; c < ACH; c += NTH) {
            int row = c / KCH, kc = (c % KCH) * 8;
            cp16(&As[(stage * BM + row) * BKP + kc],
                 A + (size_t)(bm0 + row) * K + k0 + kc);
        }
#pragma unroll
        for (int c = tid; c < BCH; c += NTH) {
            int row = c / KCH, kc = (c % KCH) * 8;
            size_t g = (size_t)(bn0 + row) * K + k0 + kc;
            cp16(&Bs[((stage * 2 + 0) * BN + row) * BKP + kc], Whi + g);
            cp16(&Bs[((stage * 2 + 1) * BN + row) * BKP + kc], Wlo + g);
        }
    };

    load_stage(0, 0);
    cp_commit();

    for (int kt = 0; kt < NK; kt++) {
        const int buf = kt & 1;
        cp_wait0();              // stage kt complete (committed last iteration)
        __syncthreads();         // publishes stage kt; separates kt-1 readers from kt+1 writes
        if (kt + 1 < NK) {
            load_stage(buf ^ 1, kt + 1);
            cp_commit();
        }

#pragma unroll
        for (int kk = 0; kk < BK / 16; kk++) {
            uint32_t a[MT][4];
#pragma unroll
            for (int i = 0; i < MT; i++)
                ldsm_x4(a[i], as_u +
                    (uint32_t)(((buf * BM + wm0 + i * 16 + a_roff) * BKP
                                + kk * 16 + a_coff) * 2));
#pragma unroll
            for (int jp = 0; jp < NT / 2; jp++) {
                uint32_t b[4];
                ldsm_x4(b, bs_u +
                    (uint32_t)((((buf * 2 + 0) * BN + wn0 + jp * 16 + b_roff) * BKP
                                + kk * 16 + b_coff) * 2));
#pragma unroll
                for (int i = 0; i < MT; i++) mma16816(acc_h[i][2 * jp],     a[i], b[0], b[1]);
#pragma unroll
                for (int i = 0; i < MT; i++) mma16816(acc_h[i][2 * jp + 1], a[i], b[2], b[3]);
            }
#pragma unroll
            for (int jp = 0; jp < NT / 2; jp++) {
                uint32_t b[4];
                ldsm_x4(b, bs_u +
                    (uint32_t)((((buf * 2 + 1) * BN + wn0 + jp * 16 + b_roff) * BKP
                                + kk * 16 + b_coff) * 2));
#pragma unroll
                for (int i = 0; i < MT; i++) mma16816(acc_l[i][2 * jp],     a[i], b[0], b[1]);
#pragma unroll
                for (int i = 0; i < MT; i++) mma16816(acc_l[i][2 * jp + 1], a[i], b[2], b[3]);
            }
        }
    }

    const int grp = lane >> 2, q = lane & 3;
#pragma unroll
    for (int i = 0; i < MT; i++) {
#pragma unroll
        for (int j = 0; j < NT; j++) {
            int row0 = bm0 + wm0 + i * 16 + grp;
            int row1 = row0 + 8;
            int col  = bn0 + wn0 + j * 8 + q * 2;
            float bv0 = bias[col];
            float bv1 = bias[col + 1];
            float v00 = fmaf(acc_l[i][j][0], LO_INV_SCALE, acc_h[i][j][0]) + bv0;
            float v01 = fmaf(acc_l[i][j][1], LO_INV_SCALE, acc_h[i][j][1]) + bv1;
            float v10 = fmaf(acc_l[i][j][2], LO_INV_SCALE, acc_h[i][j][2]) + bv0;
            float v11 = fmaf(acc_l[i][j][3], LO_INV_SCALE, acc_h[i][j][3]) + bv1;
            *(float2*)&C[(size_t)row0 * N + col] = make_float2(v00, v01);
            *(float2*)&C[(size_t)row1 * N + col] = make_float2(v10, v11);
        }
    }
}

// ====== GEMM2 (bit-packed A): C[M,64] = spikes[M,K] @ (Whi + Wlo/1024)^T + bias ======
// Round-16 config (prefetched bits, launch_bounds(128,3)) + single-sync double buffer.
// expand writes slot buf^1 (disjoint from mma(kt)'s slot buf; sync separates kt-1 readers).
#define G2_BM 64
#define G2_BK 64
#define G2_BKP 72
__global__ void __launch_bounds__(128, 3)
gemm2_bits(const uint32_t* __restrict__ Abits,
           const __half* __restrict__ Whi,
           const __half* __restrict__ Wlo,
           const float* __restrict__ bias,
           float* __restrict__ C,
           int M, int N, int K)
{
    constexpr int BM = G2_BM, BN = 64, BK = G2_BK, BKP = G2_BKP;
    constexpr int MT = 2, NT = 4;               // WM=32, WN=32
    constexpr int KCH = BK / 8;                 // 8
    constexpr int BCH = BN * KCH;               // 512

    extern __shared__ __align__(16) unsigned char smem_raw[];
    __half* As = reinterpret_cast<__half*>(smem_raw);   // [2][BM][BKP]
    __half* Bs = As + 2 * BM * BKP;                      // [2][2][BN][BKP]

    const int tid  = threadIdx.x;
    const int wid  = tid >> 5;                  // 0..3
    const int lane = tid & 31;

    const int wm0 = (wid & 1) * 32;
    const int wn0 = (wid >> 1) * 32;
    const int bm0 = blockIdx.y * BM;
    const int NK  = K / BK;
    const int KW  = K >> 5;

    const int mi = lane >> 3, rr = lane & 7;
    const int a_roff = (mi & 1) * 8 + rr;
    const int a_coff = (mi >> 1) * 8;
    const int b_roff = (mi >> 1) * 8 + rr;
    const int b_coff = (mi & 1) * 8;

    const uint32_t as_u = (uint32_t)__cvta_generic_to_shared(As);
    const uint32_t bs_u = (uint32_t)__cvta_generic_to_shared(Bs);

    const int arow = tid >> 1, ahalf = tid & 1;
    const size_t abase = (size_t)(bm0 + arow) * KW + ahalf;   // + 2*kt per stage
    __half* const adst0 = &As[arow * BKP + ahalf * 32];

    auto expand_bits = [&](int stage, uint32_t w) {
        __half* dst = adst0 + stage * BM * BKP;
#pragma unroll
        for (int g = 0; g < 8; g++) {
            uint32_t b4 = w >> (4 * g);
            uint32_t lo = ((b4 & 1) * 0x3C00u) | (((b4 >> 1) & 1) * 0x3C000000u);
            uint32_t hi = (((b4 >> 2) & 1) * 0x3C00u) | (((b4 >> 3) & 1) * 0x3C000000u);
            *(uint2*)(dst + g * 4) = make_uint2(lo, hi);
        }
    };
    auto load_b = [&](int stage, int kt) {
        const int k0 = kt * BK;
#pragma unroll
        for (int c = tid; c < BCH; c += 128) {
            int row = c / KCH, kc = (c % KCH) * 8;
            size_t g = (size_t)row * K + k0 + kc;
            cp16(&Bs[((stage * 2 + 0) * BN + row) * BKP + kc], Whi + g);
            cp16(&Bs[((stage * 2 + 1) * BN + row) * BKP + kc], Wlo + g);
        }
    };

    float acc_h[MT][NT][4];
    float acc_l[MT][NT][4];
#pragma unroll
    for (int i = 0; i < MT; i++)
#pragma unroll
        for (int j = 0; j < NT; j++)
#pragma unroll
            for (int e = 0; e < 4; e++) { acc_h[i][j][e] = 0.f; acc_l[i][j][e] = 0.f; }

    // prologue: stage 0 expanded + B in flight; bits for kt=1 prefetched
    expand_bits(0, Abits[abase]);
    load_b(0, 0);
    cp_commit();
    uint32_t w_next = Abits[abase + 2];

    for (int kt = 0; kt < NK; kt++) {
        const int buf = kt & 1;
        cp_wait0();              // stage kt B complete
        __syncthreads();         // publishes stage kt (cp.async B + ST.shared expand)
        if (kt + 1 < NK) {
            expand_bits(buf ^ 1, w_next);
            load_b(buf ^ 1, kt + 1);
            w_next = (kt + 2 < NK) ? Abits[abase + 2 * (size_t)(kt + 2)] : 0u;
            cp_commit();
        }

#pragma unroll
        for (int kk = 0; kk < BK / 16; kk++) {
            uint32_t a[MT][4];
#pragma unroll
            for (int i = 0; i < MT; i++)
                ldsm_x4(a[i], as_u +
                    (uint32_t)(((buf * BM + wm0 + i * 16 + a_roff) * BKP
                                + kk * 16 + a_coff) * 2));
#pragma unroll
            for (int jp = 0; jp < NT / 2; jp++) {
                uint32_t b[4];
                ldsm_x4(b, bs_u +
                    (uint32_t)((((buf * 2 + 0) * BN + wn0 + jp * 16 + b_roff) * BKP
                                + kk * 16 + b_coff) * 2));
#pragma unroll
                for (int i = 0; i < MT; i++) mma16816(acc_h[i][2 * jp],     a[i], b[0], b[1]);
#pragma unroll
                for (int i = 0; i < MT; i++) mma16816(acc_h[i][2 * jp + 1], a[i], b[2], b[3]);
            }
#pragma unroll
            for (int jp = 0; jp < NT / 2; jp++) {
                uint32_t b[4];
                ldsm_x4(b, bs_u +
                    (uint32_t)((((buf * 2 + 1) * BN + wn0 + jp * 16 + b_roff) * BKP
                                + kk * 16 + b_coff) * 2));
#pragma unroll
                for (int i = 0; i < MT; i++) mma16816(acc_l[i][2 * jp],     a[i], b[0], b[1]);
#pragma unroll
                for (int i = 0; i < MT; i++) mma16816(acc_l[i][2 * jp + 1], a[i], b[2], b[3]);
            }
        }
    }

    const int grp = lane >> 2, q = lane & 3;
#pragma unroll
    for (int i = 0; i < MT; i++) {
#pragma unroll
        for (int j = 0; j < NT; j++) {
            int row0 = bm0 + wm0 + i * 16 + grp;
            int row1 = row0 + 8;
            int col  = wn0 + j * 8 + q * 2;
            float bv0 = bias[col];
            float bv1 = bias[col + 1];
            float v00 = fmaf(acc_l[i][j][0], LO_INV_SCALE, acc_h[i][j][0]) + bv0;
            float v01 = fmaf(acc_l[i][j][1], LO_INV_SCALE, acc_h[i][j][1]) + bv1;
            float v10 = fmaf(acc_l[i][j][2], LO_INV_SCALE, acc_h[i][j][2]) + bv0;
            float v11 = fmaf(acc_l[i][j][3], LO_INV_SCALE, acc_h[i][j][3]) + bv1;
            *(float2*)&C[(size_t)row0 * N + col] = make_float2(v00, v01);
            *(float2*)&C[(size_t)row1 * N + col] = make_float2(v10, v11);
        }
    }
}

// ============ LIF layer 1 (4-wide): currents -> bit-packed spikes ============
__global__ void lif1_kernel(const float* __restrict__ cur, uint32_t* __restrict__ spkb) {
    int gw   = (blockIdx.x * blockDim.x + threadIdx.x) >> 5;  // warp id: 32768 total
    int lane = threadIdx.x & 31;
    int b  = gw >> 5;                 // 32 warps per batch row
    int hb = (gw & 31) << 7;          // 128 h per warp
    const size_t base = (size_t)b * HID_DIM + hb + lane;

    float mem0 = 0.f, mem1 = 0.f, mem2 = 0.f, mem3 = 0.f;
    float sp0 = 0.f, sp1 = 0.f, sp2 = 0.f, sp3 = 0.f;
#pragma unroll
    for (int t = 0; t < T_STEPS; t++) {
        const float* p = cur + (size_t)t * BATCH * HID_DIM + base;
        float c0 = p[0], c1 = p[32], c2 = p[64], c3 = p[96];
        mem0 = __fsub_rn(__fadd_rn(__fmul_rn(0.9f, mem0), c0), sp0);
        mem1 = __fsub_rn(__fadd_rn(__fmul_rn(0.9f, mem1), c1), sp1);
        mem2 = __fsub_rn(__fadd_rn(__fmul_rn(0.9f, mem2), c2), sp2);
        mem3 = __fsub_rn(__fadd_rn(__fmul_rn(0.9f, mem3), c3), sp3);
        sp0 = (mem0 > 1.0f) ? 1.f : 0.f;
        sp1 = (mem1 > 1.0f) ? 1.f : 0.f;
        sp2 = (mem2 > 1.0f) ? 1.f : 0.f;
        sp3 = (mem3 > 1.0f) ? 1.f : 0.f;
        uint32_t w0 = __ballot_sync(0xFFFFFFFFu, mem0 > 1.0f);
        uint32_t w1 = __ballot_sync(0xFFFFFFFFu, mem1 > 1.0f);
        uint32_t w2 = __ballot_sync(0xFFFFFFFFu, mem2 > 1.0f);
        uint32_t w3 = __ballot_sync(0xFFFFFFFFu, mem3 > 1.0f);
        if (lane == 0) {
            uint4 st = make_uint4(w0, w1, w2, w3);
            *(uint4*)&spkb[(size_t)(t * BATCH + b) * HIDW + (hb >> 5)] = st;
        }
    }
}

// ======================= LIF layer 2: currents -> spike counts =======================
__global__ void lif2_kernel(const float* __restrict__ cur, float* __restrict__ out) {
    int idx = blockIdx.x * blockDim.x + threadIdx.x;   // = b*OUT + o
    if (idx >= BATCH * OUT_DIM) return;
    float mem = 0.f, sp = 0.f, cnt = 0.f;
#pragma unroll
    for (int t = 0; t < T_STEPS; t++) {
        float c = cur[(size_t)t * BATCH * OUT_DIM + idx];
        mem = __fsub_rn(__fadd_rn(__fmul_rn(0.9f, mem), c), sp);
        sp  = (mem > 1.0f) ? 1.f : 0.f;
        cnt += sp;
    }
    out[idx] = cnt;
}

// ======================= launch =======================
extern "C" void kernel_launch(void* const* d_in, const int* in_sizes, int n_in,
                              void* d_out, int out_size) {
    const float* x  = (const float*)d_in[0];   // [25,1024,1024]
    const float* w1 = (const float*)d_in[1];   // [4096,1024]
    const float* b1 = (const float*)d_in[2];   // [4096]
    const float* w2 = (const float*)d_in[3];   // [64,4096]
    const float* b2 = (const float*)d_in[4];   // [64]
    float* out = (float*)d_out;                // [1024,64]

    __half *A, *w1hi, *w1lo, *w2hi, *w2lo;
    uint32_t* spkb;
    float *cur1, *cur2;
    cudaGetSymbolAddress((void**)&A,    g_A);
    cudaGetSymbolAddress((void**)&w1hi, g_w1hi);
    cudaGetSymbolAddress((void**)&w1lo, g_w1lo);
    cudaGetSymbolAddress((void**)&w2hi, g_w2hi);
    cudaGetSymbolAddress((void**)&w2lo, g_w2lo);
    cudaGetSymbolAddress((void**)&spkb, g_spkb);
    cudaGetSymbolAddress((void**)&cur1, g_cur1);
    cudaGetSymbolAddress((void**)&cur2, g_cur2);

    constexpr int SMEM1 = 2 * (128 * 72 + 2 * 64 * 72) * 2;   // 73728 B
    constexpr int SMEM2 = 2 * (64 * 72 + 2 * 64 * 72) * 2;    // 55296 B
    cudaFuncSetAttribute((const void*)gemm_hilo<128, 64, 64, 32, 32, 2>,
                         cudaFuncAttributeMaxDynamicSharedMemorySize, SMEM1);
    cudaFuncSetAttribute((const void*)gemm2_bits,
                         cudaFuncAttributeMaxDynamicSharedMemorySize, SMEM2);

    // 1) merged prep (vectorized, single launch)
    k_prep<<<4096, 256>>>((const float4*)x, (uint2*)A,
                          (const float4*)w1, (uint2*)w1hi, (uint2*)w1lo,
                          (const float4*)w2, (uint2*)w2hi, (uint2*)w2lo);

    // 2) GEMM1: cur1[25600,4096] = A[25600,1024] @ w1^T + b1  (grid 64x200)
    gemm_hilo<128, 64, 64, 32, 32, 2>
        <<<dim3(HID_DIM / 64, M_ROWS / 128), 256, SMEM1>>>(
            A, w1hi, w1lo, b1, cur1, M_ROWS, HID_DIM, IN_DIM);

    // 3) LIF layer 1 (4-wide) -> bit-packed spikes
    lif1_kernel<<<4096, 256>>>(cur1, spkb);

    // 4) GEMM2: cur2[25600,64] = spikes @ w2^T + b2  (grid 1x400)
    gemm2_bits<<<dim3(1, M_ROWS / G2_BM), 128, SMEM2>>>(
        spkb, w2hi, w2lo, b2, cur2, M_ROWS, OUT_DIM, HID_DIM);

    // 5) LIF layer 2 + spike counting
    lif2_kernel<<<(BATCH * OUT_DIM) / 256, 256>>>(cur2, out);
}